// round 10
// baseline (speedup 1.0000x reference)
#include <cuda_runtime.h>
#include <cuda_fp16.h>
#include <cstdint>

// Problem constants
#define N_TOK   4096
#define D_MODEL 1024
#define D_HID   32768
#define TOPK    128
#define EPS     1e-5f
#define CAND_MAX 256
#define MARGIN  0.012f
#define NBINS   4096
#define PREF_BIN 2880                    // bin of fp16(+0.25); rows' 128th ~0.47

// int8 quantization scales
#define SCALE_X 21.0f
#define SCALE_W 22900.0f
#define INV_SCALE (1.0f / (SCALE_X * SCALE_W))

// GEMM tiling (int8: 128B row = 128 k-elements)
#define TM   128
#define TN   128
#define TKC  128                         // k-elements per chunk
#define NCHUNK (D_MODEL / TKC)           // 8
#define TILE_BYTES 16384                 // one packed 128x128 s8 tile
#define STAGE_BYTES 32768                // A tile + B tile
#define GEMM_SMEM (2 * STAGE_BYTES)      // 64 KB

// Rescue tiling
#define RTILE 64
#define RPAD  65
#define RES_SMEM ((D_MODEL + CAND_MAX * RPAD + CAND_MAX + CAND_MAX) * 4)

// ---------------- scratch (device globals; no allocs allowed) ----------------
__device__ float  g_xn[(size_t)N_TOK * D_MODEL];           // xn fp32 (rescue + packA src)
__device__ float  g_bt[(size_t)D_HID * D_MODEL];           // w_enc^T fp32 (rescue + packB src)
// packed, pre-swizzled s8 tiles: [tileIdx][16 KB], tileIdx = blk*NCHUNK + chunk
__device__ __align__(128) char g_ap[(size_t)N_TOK * D_MODEL];
__device__ __align__(128) char g_bp[(size_t)D_HID * D_MODEL];
__device__ __half g_preh[(size_t)N_TOK * D_HID];           // 256 MB approx pre-acts
__device__ float g_mu[N_TOK];
__device__ float g_sd[N_TOK];
__device__ int   g_ci[(size_t)N_TOK * CAND_MAX];
__device__ int   g_cn[N_TOK];
__device__ float g_tv[(size_t)N_TOK * TOPK];
__device__ int   g_ti[(size_t)N_TOK * TOPK];

// ---------------- PTX helpers -------------------------------------------------
__device__ __forceinline__ uint32_t smem_u32(const void* p) {
    uint32_t a;
    asm("{ .reg .u64 t; cvta.to.shared.u64 t, %1; cvt.u32.u64 %0, t; }" : "=r"(a) : "l"(p));
    return a;
}
#define MBAR_INIT(a, n) asm volatile("mbarrier.init.shared.b64 [%0], %1;" :: "r"(a), "r"(n) : "memory")
#define MBAR_EXPECT(a, bytes) \
    asm volatile("mbarrier.arrive.expect_tx.shared.b64 _, [%0], %1;" :: "r"(a), "r"(bytes) : "memory")
#define MBAR_WAIT(a, ph) do {                                                          \
    uint32_t _m = (a), _p = (ph);                                                      \
    asm volatile("{\n\t.reg .pred P;\n\tWL_%=:\n\t"                                    \
        "mbarrier.try_wait.parity.acquire.cta.shared::cta.b64 P, [%0], %1, 0x989680;\n\t" \
        "@P bra.uni WD_%=;\n\tbra.uni WL_%=;\n\tWD_%=:\n\t}" :: "r"(_m), "r"(_p) : "memory"); \
} while (0)
__device__ __forceinline__ void bulk_cp(uint32_t dst, const void* src, uint32_t bytes, uint32_t mbar) {
    asm volatile(
        "cp.async.bulk.shared::cluster.global.mbarrier::complete_tx::bytes [%0], [%1], %2, [%3];"
        :: "r"(dst), "l"(src), "r"(bytes), "r"(mbar) : "memory");
}

#define LDSM4(R0, R1, R2, R3, A)                                                  \
    asm volatile("ldmatrix.sync.aligned.m8n8.x4.shared.b16 {%0,%1,%2,%3}, [%4];"  \
        : "=r"(R0), "=r"(R1), "=r"(R2), "=r"(R3) : "r"(A))

// int8 IMMA: m16n8k32, s32 accumulate (sm_80 baseline, HW-native).
// Fragment byte layout identical to fp16 m16n8k16 (each b16 slot = 2 s8).
#define MMAS8(D, A, B0, B1)                                                       \
    asm volatile("mma.sync.aligned.m16n8k32.row.col.s32.s8.s8.s32 "               \
        "{%0,%1,%2,%3}, {%4,%5,%6,%7}, {%8,%9}, {%0,%1,%2,%3};"                   \
        : "+r"((D)[0]), "+r"((D)[1]), "+r"((D)[2]), "+r"((D)[3])                   \
        : "r"((A)[0]), "r"((A)[1]), "r"((A)[2]), "r"((A)[3]), "r"(B0), "r"(B1))

// ---------------- LayerNorm ----------------------------------------------------
__device__ __forceinline__ float block_reduce_sum256(float v, float* red) {
    #pragma unroll
    for (int o = 16; o > 0; o >>= 1) v += __shfl_xor_sync(0xffffffffu, v, o);
    int w = threadIdx.x >> 5;
    if ((threadIdx.x & 31) == 0) red[w] = v;
    __syncthreads();
    float r = (threadIdx.x < 8) ? red[threadIdx.x] : 0.f;
    if (threadIdx.x < 32) {
        #pragma unroll
        for (int o = 4; o > 0; o >>= 1) r += __shfl_xor_sync(0xffffffffu, r, o);
        if (threadIdx.x == 0) red[0] = r;
    }
    __syncthreads();
    float out = red[0];
    __syncthreads();
    return out;
}

__global__ __launch_bounds__(256) void ln_kernel(const float* __restrict__ x,
                                                 const float* __restrict__ b_pre) {
    __shared__ float sx[D_MODEL];
    __shared__ float red[32];
    const int row = blockIdx.x;
    const int t = threadIdx.x;
    const float* xr = x + (size_t)row * D_MODEL;

    float sum = 0.f;
    #pragma unroll
    for (int q = 0; q < 4; q++) { float f = xr[t + q * 256]; sx[t + q * 256] = f; sum += f; }
    float m = block_reduce_sum256(sum, red) * (1.0f / D_MODEL);

    float sq = 0.f;
    #pragma unroll
    for (int q = 0; q < 4; q++) { float c = sx[t + q * 256] - m; sq += c * c; }
    float sd = sqrtf(block_reduce_sum256(sq, red) * (1.0f / (D_MODEL - 1)));
    float inv = 1.0f / (sd + EPS);

    #pragma unroll
    for (int q = 0; q < 4; q++) {
        int col = t + q * 256;
        g_xn[(size_t)row * D_MODEL + col] = (sx[col] - m) * inv - b_pre[col];
    }
    if (t == 0) { g_mu[row] = m; g_sd[row] = sd; }
}

// ---------------- transpose: w_enc -> [D_HID, D_MODEL] fp32 -------------------
__global__ __launch_bounds__(256) void transpose_kernel(const float* __restrict__ w) {
    __shared__ float tile[32][33];
    const int n0 = blockIdx.x * 32, k0 = blockIdx.y * 32;
    const int tx = threadIdx.x, ty = threadIdx.y;
    #pragma unroll
    for (int i = 0; i < 32; i += 8)
        tile[ty + i][tx] = w[(size_t)(k0 + ty + i) * D_HID + n0 + tx];
    __syncthreads();
    #pragma unroll
    for (int i = 0; i < 32; i += 8)
        g_bt[(size_t)(n0 + ty + i) * D_MODEL + k0 + tx] = tile[tx][ty + i];
}

// ---------------- pack: fp32 rows -> pre-swizzled s8 16KB tiles ---------------
// Tile (blk, c): rows blk*128..+127, k = c*128..+127 (quantized by `scale`).
// In-tile offset for (r, 16B-group eg): r*128 + ((eg ^ (r&7))*16) — the exact
// XOR-swizzled smem image, so one contiguous bulk copy lands ready for ldmatrix.
__global__ __launch_bounds__(256) void pack8_kernel(const float* __restrict__ src,
                                                    char* __restrict__ dst,
                                                    float scale) {
    const int blk = blockIdx.x, c = blockIdx.y;
    const int t = threadIdx.x;
    char* tile = dst + ((size_t)blk * NCHUNK + c) * TILE_BYTES;
    #pragma unroll
    for (int gi = 0; gi < 4; gi++) {
        const int g = t + gi * 256;           // 16B group id, 0..1023
        const int r = g >> 3, eg = g & 7;
        const float* s = src + (size_t)(blk * 128 + r) * D_MODEL + c * 128 + eg * 16;
        uint32_t w[4];
        #pragma unroll
        for (int j = 0; j < 4; j++) {
            int q0 = __float2int_rn(fminf(fmaxf(s[4*j + 0] * scale, -127.f), 127.f));
            int q1 = __float2int_rn(fminf(fmaxf(s[4*j + 1] * scale, -127.f), 127.f));
            int q2 = __float2int_rn(fminf(fmaxf(s[4*j + 2] * scale, -127.f), 127.f));
            int q3 = __float2int_rn(fminf(fmaxf(s[4*j + 3] * scale, -127.f), 127.f));
            w[j] = (q0 & 0xFF) | ((q1 & 0xFF) << 8) | ((q2 & 0xFF) << 16) | ((q3 & 0xFF) << 24);
        }
        *reinterpret_cast<uint4*>(tile + r * 128 + ((eg ^ (r & 7)) * 16)) =
            *reinterpret_cast<uint4*>(w);
    }
}

// ---------------- IMMA GEMM: bulk-copy pipeline -------------------------------
__global__ __launch_bounds__(256, 2) void enc_gemm_mma(const float* __restrict__ bias) {
    extern __shared__ __align__(1024) char smem[];
    const uint32_t sb = smem_u32(smem);
    __shared__ __align__(8) uint64_t mbar_store[2];
    const uint32_t mb0 = smem_u32(&mbar_store[0]);
    const uint32_t mb1 = smem_u32(&mbar_store[1]);

    const int t = threadIdx.x;
    const int wid = t >> 5, lane = t & 31;
    const int wm = wid >> 1, wn = wid & 1;      // 4x2 warps, warp tile 32x64
    const int Mblk = blockIdx.x;
    const int Nblk = blockIdx.y;
    const int bm = Mblk * TM;
    const int bn = Nblk * TN;

    if (t == 0) { MBAR_INIT(mb0, 1); MBAR_INIT(mb1, 1); }
    __syncthreads();

    int acc[2][8][4];
    #pragma unroll
    for (int i = 0; i < 2; i++)
        #pragma unroll
        for (int j = 0; j < 8; j++)
            #pragma unroll
            for (int q = 0; q < 4; q++) acc[i][j][q] = 0;

    const int laneA = lane & 15;
    const int hiA   = lane >> 4;
    const int rBoff = (lane & 7) + ((lane >> 4) << 3);
    const int hiB   = (lane >> 3) & 1;

    const char* Abase = g_ap + (size_t)Mblk * NCHUNK * TILE_BYTES;
    const char* Bbase = g_bp + (size_t)Nblk * NCHUNK * TILE_BYTES;

    if (t == 0) {
        MBAR_EXPECT(mb0, STAGE_BYTES);
        bulk_cp(sb,         Abase, TILE_BYTES, mb0);
        bulk_cp(sb + 16384, Bbase, TILE_BYTES, mb0);
    }

    for (int c = 0; c < NCHUNK; c++) {
        const int s = c & 1;
        if (c + 1 < NCHUNK && t == 0) {
            const uint32_t mbN = (s ? mb0 : mb1);
            const uint32_t stN = sb + (uint32_t)(1 - s) * STAGE_BYTES;
            MBAR_EXPECT(mbN, STAGE_BYTES);
            bulk_cp(stN,         Abase + (size_t)(c + 1) * TILE_BYTES, TILE_BYTES, mbN);
            bulk_cp(stN + 16384, Bbase + (size_t)(c + 1) * TILE_BYTES, TILE_BYTES, mbN);
        }
        MBAR_WAIT(s ? mb1 : mb0, (c >> 1) & 1);

        const uint32_t base = sb + (uint32_t)s * STAGE_BYTES;
        const uint32_t Ah = base, Bh = base + 16384;

        #pragma unroll
        for (int ks = 0; ks < 4; ks++) {       // each ks = 32 s8 k-elements (32 B)
            const int c0 = ks * 2;
            uint32_t aH[2][4], bH[8][2];
            #pragma unroll
            for (int tm = 0; tm < 2; tm++) {
                int r = wm * 32 + tm * 16 + laneA;
                uint32_t off = (uint32_t)r * 128 + (uint32_t)((((c0 + hiA) ^ (r & 7))) * 16);
                LDSM4(aH[tm][0], aH[tm][1], aH[tm][2], aH[tm][3], Ah + off);
            }
            #pragma unroll
            for (int tp = 0; tp < 4; tp++) {
                int r = wn * 64 + tp * 16 + rBoff;
                uint32_t off = (uint32_t)r * 128 + (uint32_t)((((c0 + hiB) ^ (r & 7))) * 16);
                LDSM4(bH[2*tp][0], bH[2*tp][1], bH[2*tp+1][0], bH[2*tp+1][1], Bh + off);
            }
            #pragma unroll
            for (int tm = 0; tm < 2; tm++)
                #pragma unroll
                for (int tn = 0; tn < 8; tn++)
                    MMAS8(acc[tm][tn], aH[tm], bH[tn][0], bH[tn][1]);
        }
        __syncthreads();
    }

    // epilogue: dequantize, add bias, store fp16
    const int gid = lane >> 2, tig = lane & 3;
    #pragma unroll
    for (int tm = 0; tm < 2; tm++) {
        const int r0 = bm + wm * 32 + tm * 16 + gid;
        #pragma unroll
        for (int tn = 0; tn < 8; tn++) {
            const int col = bn + wn * 64 + tn * 8 + tig * 2;
            const float b0 = __ldg(&bias[col]);
            const float b1 = __ldg(&bias[col + 1]);
            __half2 h0 = __floats2half2_rn((float)acc[tm][tn][0] * INV_SCALE + b0,
                                           (float)acc[tm][tn][1] * INV_SCALE + b1);
            __half2 h1 = __floats2half2_rn((float)acc[tm][tn][2] * INV_SCALE + b0,
                                           (float)acc[tm][tn][3] * INV_SCALE + b1);
            *reinterpret_cast<__half2*>(&g_preh[(size_t)r0 * D_HID + col]) = h0;
            *reinterpret_cast<__half2*>(&g_preh[(size_t)(r0 + 8) * D_HID + col]) = h1;
        }
    }
}

// ---------------- topk: fp16-key histogram select + candidate collection ------
__device__ __forceinline__ int bin_of_half_bits(uint32_t h) {
    uint32_t k = (h & 0x8000u) ? ((~h) & 0xFFFFu) : (h | 0x8000u);
    return (int)(k >> 4);
}

__global__ __launch_bounds__(256) void topk_kernel() {
    __shared__ int hist[NBINS];            // 16 KB
    __shared__ int segs[256];
    __shared__ int warpTot[8];
    __shared__ float s_thr;
    __shared__ int s_cnt;

    const int row = blockIdx.x;
    const int t = threadIdx.x;
    const int lane = t & 31, wid = t >> 5;
    const uint4* p4 = reinterpret_cast<const uint4*>(g_preh + (size_t)row * D_HID);

    if (t == 0) s_cnt = 0;

    // Histogram with prefilter (only bins >= PREF_BIN, ~0.4% of elements).
    // Fallback: if the suffix above the prefilter can't cover TOPK, redo full.
    int total = 0;
    for (int attempt = 0; attempt < 2; attempt++) {
        const int pref = (attempt == 0) ? PREF_BIN : 0;
        #pragma unroll
        for (int i = 0; i < NBINS / 256; i++) hist[t + i * 256] = 0;
        __syncthreads();
        #pragma unroll
        for (int i = 0; i < D_HID / 8 / 256; i++) {
            uint4 v = p4[t + i * 256];
            int b;
            b = bin_of_half_bits(v.x & 0xFFFFu); if (b >= pref) atomicAdd(&hist[b], 1);
            b = bin_of_half_bits(v.x >> 16);     if (b >= pref) atomicAdd(&hist[b], 1);
            b = bin_of_half_bits(v.y & 0xFFFFu); if (b >= pref) atomicAdd(&hist[b], 1);
            b = bin_of_half_bits(v.y >> 16);     if (b >= pref) atomicAdd(&hist[b], 1);
            b = bin_of_half_bits(v.z & 0xFFFFu); if (b >= pref) atomicAdd(&hist[b], 1);
            b = bin_of_half_bits(v.z >> 16);     if (b >= pref) atomicAdd(&hist[b], 1);
            b = bin_of_half_bits(v.w & 0xFFFFu); if (b >= pref) atomicAdd(&hist[b], 1);
            b = bin_of_half_bits(v.w >> 16);     if (b >= pref) atomicAdd(&hist[b], 1);
        }
        __syncthreads();

        int seg = 0;
        #pragma unroll
        for (int k = 0; k < 16; k++) seg += hist[t * 16 + k];
        segs[t] = seg;
        int wsum = seg;
        #pragma unroll
        for (int o = 16; o > 0; o >>= 1) wsum += __shfl_xor_sync(0xffffffffu, wsum, o);
        if (lane == 0) warpTot[wid] = wsum;
        __syncthreads();
        total = warpTot[0] + warpTot[1] + warpTot[2] + warpTot[3]
              + warpTot[4] + warpTot[5] + warpTot[6] + warpTot[7];
        if (total >= TOPK) break;
        __syncthreads();
    }

    if (t == 0) {
        int cum = 0, w = 7;
        for (; w > 0; w--) { if (cum + warpTot[w] >= TOPK) break; cum += warpTot[w]; }
        int s = w * 32 + 31;
        for (; s > w * 32; s--) { if (cum + segs[s] >= TOPK) break; cum += segs[s]; }
        int b = s * 16 + 15;
        for (; b > s * 16; b--) { if (cum + hist[b] >= TOPK) break; cum += hist[b]; }
        uint32_t keyLo = (uint32_t)b << 4;
        uint32_t hbits = (keyLo & 0x8000u) ? (keyLo & 0x7FFFu) : ((~keyLo) & 0xFFFFu);
        __half_raw hr; hr.x = (unsigned short)hbits;
        s_thr = __half2float(__half(hr)) - MARGIN;
    }
    __syncthreads();

    const float thr = s_thr;
    const __half* p = g_preh + (size_t)row * D_HID;
    for (int i = t; i < D_HID; i += 256) {
        if (__half2float(p[i]) >= thr) {
            int pos = atomicAdd(&s_cnt, 1);
            if (pos < CAND_MAX) g_ci[(size_t)row * CAND_MAX + pos] = i;
        }
    }
    __syncthreads();
    if (t == 0) g_cn[row] = (s_cnt < CAND_MAX) ? s_cnt : CAND_MAX;
}

// ---------------- rescue: exact fp32 dots (R1-identical order) + top-128 ------
__global__ __launch_bounds__(256, 2) void rescue_kernel(const float* __restrict__ b_enc) {
    extern __shared__ float dyn[];
    float* sx = dyn;                                   // [D_MODEL]
    float* sw = dyn + D_MODEL;                         // [CAND_MAX][RPAD]
    float* sv = sw + CAND_MAX * RPAD;                  // [CAND_MAX]
    int*   si = (int*)(sv + CAND_MAX);                 // [CAND_MAX]

    const int row = blockIdx.x;
    const int t = threadIdx.x;

    #pragma unroll
    for (int q = 0; q < 4; q++)
        sx[t + q * 256] = g_xn[(size_t)row * D_MODEL + t + q * 256];
    si[t] = (t < g_cn[row]) ? g_ci[(size_t)row * CAND_MAX + t] : 0x7FFFFFFF;
    __syncthreads();
    const int C = g_cn[row];
    const int myIdx = si[t];

    float acc = 0.f;
    for (int k0 = 0; k0 < D_MODEL; k0 += RTILE) {
        const int q = t & 15;                // 16 float4 = 64 floats
        #pragma unroll
        for (int pass = 0; pass < 16; pass++) {
            const int c = pass * 16 + (t >> 4);
            if (c < C) {
                const float4 v = *reinterpret_cast<const float4*>(
                    g_bt + (size_t)si[c] * D_MODEL + k0 + q * 4);
                float* dst = sw + c * RPAD + q * 4;
                dst[0] = v.x; dst[1] = v.y; dst[2] = v.z; dst[3] = v.w;
            }
        }
        __syncthreads();
        if (t < C) {
            const float* wrow = sw + t * RPAD;
            #pragma unroll
            for (int kk = 0; kk < RTILE; kk++)
                acc = fmaf(sx[k0 + kk], wrow[kk], acc);   // strict sequential chain
        }
        __syncthreads();
    }

    if (t < C) {
        sv[t] = acc + __ldg(&b_enc[myIdx]);
    } else {
        sv[t] = -__int_as_float(0x7F800000);   // -inf
    }
    __syncthreads();

    // bitonic sort 256: val desc, idx asc (jax tie order)
    #pragma unroll 1
    for (int k = 2; k <= CAND_MAX; k <<= 1) {
        #pragma unroll 1
        for (int j = k >> 1; j > 0; j >>= 1) {
            const int ixj = t ^ j;
            if (ixj > t) {
                float v0 = sv[t], v1 = sv[ixj];
                int i0 = si[t], i1 = si[ixj];
                bool firstWins = (v0 > v1) || (v0 == v1 && i0 < i1);
                if (((t & k) == 0) != firstWins) {
                    sv[t] = v1; sv[ixj] = v0;
                    si[t] = i1; si[ixj] = i0;
                }
            }
            __syncthreads();
        }
    }

    if (t < TOPK) {
        g_tv[(size_t)row * TOPK + t] = fmaxf(sv[t], 0.0f);
        g_ti[(size_t)row * TOPK + t] = si[t];
    }
}

// ---------------- sparse decode + de-normalize -------------------------------
__global__ __launch_bounds__(256) void decode_kernel(const float* __restrict__ w_dec,
                                                     const float* __restrict__ b_pre,
                                                     float* __restrict__ out) {
    __shared__ float sval[TOPK];
    __shared__ int   sidx[TOPK];
    const int row = blockIdx.x;
    const int t = threadIdx.x;
    if (t < TOPK) {
        sval[t] = g_tv[(size_t)row * TOPK + t];
        sidx[t] = g_ti[(size_t)row * TOPK + t];
    }
    __syncthreads();

    float acc0 = 0.f, acc1 = 0.f, acc2 = 0.f, acc3 = 0.f;
    #pragma unroll 4
    for (int j = 0; j < TOPK; j++) {
        const float v = sval[j];
        const float* wr = w_dec + (size_t)sidx[j] * D_MODEL;
        acc0 += v * __ldg(&wr[t]);
        acc1 += v * __ldg(&wr[t + 256]);
        acc2 += v * __ldg(&wr[t + 512]);
        acc3 += v * __ldg(&wr[t + 768]);
    }
    const float m = g_mu[row], s = g_sd[row];
    float* o = out + (size_t)row * D_MODEL;
    o[t]       = (acc0 + b_pre[t])       * s + m;
    o[t + 256] = (acc1 + b_pre[t + 256]) * s + m;
    o[t + 512] = (acc2 + b_pre[t + 512]) * s + m;
    o[t + 768] = (acc3 + b_pre[t + 768]) * s + m;
}

// ---------------- launch ------------------------------------------------------
extern "C" void kernel_launch(void* const* d_in, const int* in_sizes, int n_in,
                              void* d_out, int out_size) {
    const float* x     = (const float*)d_in[0];
    const float* w_enc = (const float*)d_in[1];
    const float* w_dec = (const float*)d_in[2];
    const float* b_enc = (const float*)d_in[3];
    const float* b_pre = (const float*)d_in[4];
    float* out = (float*)d_out;

    float* d_xn; cudaGetSymbolAddress((void**)&d_xn, g_xn);
    float* d_bt; cudaGetSymbolAddress((void**)&d_bt, g_bt);
    char* d_ap; cudaGetSymbolAddress((void**)&d_ap, g_ap);
    char* d_bp; cudaGetSymbolAddress((void**)&d_bp, g_bp);

    // 1. LayerNorm (fp32 out)
    ln_kernel<<<N_TOK, 256>>>(x, b_pre);

    // 2. Transpose w_enc -> fp32 [D_HID, D_MODEL]
    dim3 tg(D_HID / 32, D_MODEL / 32);
    transpose_kernel<<<tg, dim3(32, 8)>>>(w_enc);

    // 3. Pack fp32 -> pre-swizzled s8 16KB tiles
    pack8_kernel<<<dim3(N_TOK / 128, NCHUNK), 256>>>(d_xn, d_ap, SCALE_X);
    pack8_kernel<<<dim3(D_HID / 128, NCHUNK), 256>>>(d_bt, d_bp, SCALE_W);

    // 4. int8 IMMA encoder GEMM with cp.async.bulk pipeline
    cudaFuncSetAttribute(enc_gemm_mma, cudaFuncAttributeMaxDynamicSharedMemorySize, GEMM_SMEM);
    dim3 ggrid(N_TOK / TM, D_HID / TN);
    enc_gemm_mma<<<ggrid, 256, GEMM_SMEM>>>(b_enc);

    // 5. Prefiltered histogram-select approx top-128 + margin candidates
    topk_kernel<<<N_TOK, 256>>>();

    // 6. Rescue: R1-identical sequential fp32 dots, smem-staged coalesced loads
    cudaFuncSetAttribute(rescue_kernel, cudaFuncAttributeMaxDynamicSharedMemorySize, RES_SMEM);
    rescue_kernel<<<N_TOK, 256, RES_SMEM>>>(b_enc);

    // 7. Sparse decode + un-normalize
    decode_kernel<<<N_TOK, 256>>>(w_dec, b_pre, out);
}

// round 12
// speedup vs baseline: 1.7702x; 1.7702x over previous
#include <cuda_runtime.h>
#include <cuda_fp16.h>
#include <cstdint>

// Problem constants
#define N_TOK   4096
#define D_MODEL 1024
#define D_HID   32768
#define TOPK    128
#define EPS     1e-5f
#define CAND_MAX 256
#define MARGIN  4e-3f
#define NBINS   4096
#define PREF_BIN 2880                    // bin of fp16(+0.25); rows' 128th ~0.47

// GEMM tiling (fp16)
#define TM   128
#define TN   128
#define TKC  64                          // k-halfs per chunk
#define NCHUNK (D_MODEL / TKC)           // 16
#define TILE_BYTES 16384                 // one packed 128x64 fp16 tile
#define STAGE_BYTES 32768                // A tile + B tile
#define GEMM_SMEM (2 * STAGE_BYTES)      // 64 KB

// Rescue tiling
#define RTILE 64
#define RPAD  65
#define RES_SMEM ((D_MODEL + CAND_MAX * RPAD + CAND_MAX + CAND_MAX) * 4)

// ---------------- scratch (device globals; no allocs allowed) ----------------
__device__ float  g_xn[(size_t)N_TOK * D_MODEL];           // xn fp32 (rescue)
__device__ float  g_bt[(size_t)D_HID * D_MODEL];           // w_enc^T fp32 (rescue)
__device__ __align__(128) __half g_ap[(size_t)N_TOK * D_MODEL];   // packed swizzled A
__device__ __align__(128) __half g_bp[(size_t)D_HID * D_MODEL];   // packed swizzled B
__device__ __half g_preh[(size_t)N_TOK * D_HID];           // 256 MB approx pre-acts
__device__ float g_mu[N_TOK];
__device__ float g_sd[N_TOK];
__device__ int   g_ci[(size_t)N_TOK * CAND_MAX];
__device__ int   g_cn[N_TOK];
__device__ float g_tv[(size_t)N_TOK * TOPK];
__device__ int   g_ti[(size_t)N_TOK * TOPK];

// ---------------- PTX helpers -------------------------------------------------
__device__ __forceinline__ uint32_t smem_u32(const void* p) {
    uint32_t a;
    asm("{ .reg .u64 t; cvta.to.shared.u64 t, %1; cvt.u32.u64 %0, t; }" : "=r"(a) : "l"(p));
    return a;
}
#define MBAR_INIT(a, n) asm volatile("mbarrier.init.shared.b64 [%0], %1;" :: "r"(a), "r"(n) : "memory")
#define MBAR_EXPECT(a, bytes) \
    asm volatile("mbarrier.arrive.expect_tx.shared.b64 _, [%0], %1;" :: "r"(a), "r"(bytes) : "memory")
#define MBAR_WAIT(a, ph) do {                                                          \
    uint32_t _m = (a), _p = (ph);                                                      \
    asm volatile("{\n\t.reg .pred P;\n\tWL_%=:\n\t"                                    \
        "mbarrier.try_wait.parity.acquire.cta.shared::cta.b64 P, [%0], %1, 0x989680;\n\t" \
        "@P bra.uni WD_%=;\n\tbra.uni WL_%=;\n\tWD_%=:\n\t}" :: "r"(_m), "r"(_p) : "memory"); \
} while (0)
__device__ __forceinline__ void bulk_cp(uint32_t dst, const void* src, uint32_t bytes, uint32_t mbar) {
    asm volatile(
        "cp.async.bulk.shared::cluster.global.mbarrier::complete_tx::bytes [%0], [%1], %2, [%3];"
        :: "r"(dst), "l"(src), "r"(bytes), "r"(mbar) : "memory");
}

#define LDSM4(R0, R1, R2, R3, A)                                                  \
    asm volatile("ldmatrix.sync.aligned.m8n8.x4.shared.b16 {%0,%1,%2,%3}, [%4];"  \
        : "=r"(R0), "=r"(R1), "=r"(R2), "=r"(R3) : "r"(A))

#define MMA16816(D, A, B0, B1)                                                    \
    asm volatile("mma.sync.aligned.m16n8k16.row.col.f32.f16.f16.f32 "             \
        "{%0,%1,%2,%3}, {%4,%5,%6,%7}, {%8,%9}, {%0,%1,%2,%3};"                   \
        : "+f"((D)[0]), "+f"((D)[1]), "+f"((D)[2]), "+f"((D)[3])                   \
        : "r"((A)[0]), "r"((A)[1]), "r"((A)[2]), "r"((A)[3]), "r"(B0), "r"(B1))

// ---------------- LayerNorm + direct packed-A write ---------------------------
__device__ __forceinline__ float block_reduce_sum256(float v, float* red) {
    #pragma unroll
    for (int o = 16; o > 0; o >>= 1) v += __shfl_xor_sync(0xffffffffu, v, o);
    int w = threadIdx.x >> 5;
    if ((threadIdx.x & 31) == 0) red[w] = v;
    __syncthreads();
    float r = (threadIdx.x < 8) ? red[threadIdx.x] : 0.f;
    if (threadIdx.x < 32) {
        #pragma unroll
        for (int o = 4; o > 0; o >>= 1) r += __shfl_xor_sync(0xffffffffu, r, o);
        if (threadIdx.x == 0) red[0] = r;
    }
    __syncthreads();
    float out = red[0];
    __syncthreads();
    return out;
}

__global__ __launch_bounds__(256) void ln_kernel(const float* __restrict__ x,
                                                 const float* __restrict__ b_pre) {
    __shared__ float sx[D_MODEL];
    __shared__ float red[32];
    const int row = blockIdx.x;
    const int t = threadIdx.x;
    const float* xr = x + (size_t)row * D_MODEL;

    float sum = 0.f;
    #pragma unroll
    for (int q = 0; q < 4; q++) { float f = xr[t + q * 256]; sx[t + q * 256] = f; sum += f; }
    float m = block_reduce_sum256(sum, red) * (1.0f / D_MODEL);

    float sq = 0.f;
    #pragma unroll
    for (int q = 0; q < 4; q++) { float c = sx[t + q * 256] - m; sq += c * c; }
    float sd = sqrtf(block_reduce_sum256(sq, red) * (1.0f / (D_MODEL - 1)));
    float inv = 1.0f / (sd + EPS);

    // write fp32 xn; overwrite sx with normalized value for the pack step
    #pragma unroll
    for (int q = 0; q < 4; q++) {
        int col = t + q * 256;
        float v = (sx[col] - m) * inv - b_pre[col];
        g_xn[(size_t)row * D_MODEL + col] = v;
        sx[col] = v;
    }
    if (t == 0) { g_mu[row] = m; g_sd[row] = sd; }
    __syncthreads();

    // pack: 128 threads x one 16B group (8 halfs) into swizzled tile image
    if (t < 128) {
        const int c = t >> 3;            // k-chunk 0..15
        const int eg = t & 7;            // 16B group within 128B row
        const int k = t * 8;
        __half2 h[4];
        #pragma unroll
        for (int j = 0; j < 4; j++)
            h[j] = __floats2half2_rn(sx[k + 2*j], sx[k + 2*j + 1]);
        const int blk = row >> 7, r = row & 127;
        char* tile = (char*)g_ap + ((size_t)blk * NCHUNK + c) * TILE_BYTES;
        *reinterpret_cast<uint4*>(tile + r * 128 + ((eg ^ (r & 7)) * 16)) =
            *reinterpret_cast<uint4*>(h);
    }
}

// ---------------- fused transpose + pack: w_enc -> g_bt fp32 + g_bp fp16 ------
// tile[a][b] = w[k0+a][n0+b]  (first index = k_local, second = n_local)
__global__ __launch_bounds__(256) void transpose_pack_kernel(const float* __restrict__ w) {
    __shared__ float tile[32][33];
    const int n0 = blockIdx.x * 32, k0 = blockIdx.y * 32;
    const int tx = threadIdx.x, ty = threadIdx.y;
    const int t = ty * 32 + tx;
    #pragma unroll
    for (int i = 0; i < 32; i += 8)
        tile[ty + i][tx] = w[(size_t)(k0 + ty + i) * D_HID + n0 + tx];
    __syncthreads();
    // fp32 transposed write (coalesced in k): g_bt[n][k] = tile[k_local][n_local]
    #pragma unroll
    for (int i = 0; i < 32; i += 8)
        g_bt[(size_t)(n0 + ty + i) * D_MODEL + k0 + tx] = tile[tx][ty + i];
    // fp16 packed swizzled write: 128 tasks (32 n-rows x 4 groups of 8 k)
    // NOTE: tile's first index is k_local -> read tile[k_local][r].
    if (t < 128) {
        const int r = t >> 2;            // local n row 0..31
        const int gq = t & 3;            // 8-k group 0..3
        const int n = n0 + r;
        const int k = k0 + gq * 8;
        __half2 h[4];
        #pragma unroll
        for (int j = 0; j < 4; j++)
            h[j] = __floats2half2_rn(tile[gq*8 + 2*j][r] * 256.0f,
                                     tile[gq*8 + 2*j + 1][r] * 256.0f);
        const int blk = n >> 7, c = k >> 6;
        const int r128 = n & 127;
        const int eg = (k & 63) >> 3;
        char* tp = (char*)g_bp + ((size_t)blk * NCHUNK + c) * TILE_BYTES;
        *reinterpret_cast<uint4*>(tp + r128 * 128 + ((eg ^ (r128 & 7)) * 16)) =
            *reinterpret_cast<uint4*>(h);
    }
}

// ---------------- HMMA GEMM: bulk-copy pipeline (R9, proven) ------------------
__global__ __launch_bounds__(256, 2) void enc_gemm_mma(const float* __restrict__ bias) {
    extern __shared__ __align__(1024) char smem[];
    const uint32_t sb = smem_u32(smem);
    __shared__ __align__(8) uint64_t mbar_store[2];
    const uint32_t mb0 = smem_u32(&mbar_store[0]);
    const uint32_t mb1 = smem_u32(&mbar_store[1]);

    const int t = threadIdx.x;
    const int wid = t >> 5, lane = t & 31;
    const int wm = wid >> 1, wn = wid & 1;      // 4x2 warps, warp tile 32x64
    const int Mblk = blockIdx.x;
    const int Nblk = blockIdx.y;
    const int bm = Mblk * TM;
    const int bn = Nblk * TN;

    if (t == 0) { MBAR_INIT(mb0, 1); MBAR_INIT(mb1, 1); }
    __syncthreads();

    float acc[2][8][4];
    #pragma unroll
    for (int i = 0; i < 2; i++)
        #pragma unroll
        for (int j = 0; j < 8; j++)
            #pragma unroll
            for (int q = 0; q < 4; q++) acc[i][j][q] = 0.f;

    const int laneA = lane & 15;
    const int hiA   = lane >> 4;
    const int rBoff = (lane & 7) + ((lane >> 4) << 3);
    const int hiB   = (lane >> 3) & 1;

    const char* Abase = (const char*)g_ap + (size_t)Mblk * NCHUNK * TILE_BYTES;
    const char* Bbase = (const char*)g_bp + (size_t)Nblk * NCHUNK * TILE_BYTES;

    if (t == 0) {
        MBAR_EXPECT(mb0, STAGE_BYTES);
        bulk_cp(sb,         Abase, TILE_BYTES, mb0);
        bulk_cp(sb + 16384, Bbase, TILE_BYTES, mb0);
    }

    for (int c = 0; c < NCHUNK; c++) {
        const int s = c & 1;
        if (c + 1 < NCHUNK && t == 0) {
            const uint32_t mbN = (s ? mb0 : mb1);
            const uint32_t stN = sb + (uint32_t)(1 - s) * STAGE_BYTES;
            MBAR_EXPECT(mbN, STAGE_BYTES);
            bulk_cp(stN,         Abase + (size_t)(c + 1) * TILE_BYTES, TILE_BYTES, mbN);
            bulk_cp(stN + 16384, Bbase + (size_t)(c + 1) * TILE_BYTES, TILE_BYTES, mbN);
        }
        MBAR_WAIT(s ? mb1 : mb0, (c >> 1) & 1);

        const uint32_t base = sb + (uint32_t)s * STAGE_BYTES;
        const uint32_t Ah = base, Bh = base + 16384;

        #pragma unroll
        for (int ks = 0; ks < 4; ks++) {
            const int c0 = ks * 2;
            uint32_t aH[2][4], bH[8][2];
            #pragma unroll
            for (int tm = 0; tm < 2; tm++) {
                int r = wm * 32 + tm * 16 + laneA;
                uint32_t off = (uint32_t)r * 128 + (uint32_t)((((c0 + hiA) ^ (r & 7))) * 16);
                LDSM4(aH[tm][0], aH[tm][1], aH[tm][2], aH[tm][3], Ah + off);
            }
            #pragma unroll
            for (int tp = 0; tp < 4; tp++) {
                int r = wn * 64 + tp * 16 + rBoff;
                uint32_t off = (uint32_t)r * 128 + (uint32_t)((((c0 + hiB) ^ (r & 7))) * 16);
                LDSM4(bH[2*tp][0], bH[2*tp][1], bH[2*tp+1][0], bH[2*tp+1][1], Bh + off);
            }
            #pragma unroll
            for (int tm = 0; tm < 2; tm++)
                #pragma unroll
                for (int tn = 0; tn < 8; tn++)
                    MMA16816(acc[tm][tn], aH[tm], bH[tn][0], bH[tn][1]);
        }
        __syncthreads();
    }

    // epilogue: unscale (B was x256), add bias, store fp16
    const float inv256 = 1.0f / 256.0f;
    const int gid = lane >> 2, tig = lane & 3;
    #pragma unroll
    for (int tm = 0; tm < 2; tm++) {
        const int r0 = bm + wm * 32 + tm * 16 + gid;
        #pragma unroll
        for (int tn = 0; tn < 8; tn++) {
            const int col = bn + wn * 64 + tn * 8 + tig * 2;
            const float b0 = __ldg(&bias[col]);
            const float b1 = __ldg(&bias[col + 1]);
            __half2 h0 = __floats2half2_rn(acc[tm][tn][0] * inv256 + b0,
                                           acc[tm][tn][1] * inv256 + b1);
            __half2 h1 = __floats2half2_rn(acc[tm][tn][2] * inv256 + b0,
                                           acc[tm][tn][3] * inv256 + b1);
            *reinterpret_cast<__half2*>(&g_preh[(size_t)r0 * D_HID + col]) = h0;
            *reinterpret_cast<__half2*>(&g_preh[(size_t)(r0 + 8) * D_HID + col]) = h1;
        }
    }
}

// ---------------- topk: prefiltered fp16-key histogram select -----------------
__device__ __forceinline__ int bin_of_half_bits(uint32_t h) {
    uint32_t k = (h & 0x8000u) ? ((~h) & 0xFFFFu) : (h | 0x8000u);
    return (int)(k >> 4);
}

__global__ __launch_bounds__(256) void topk_kernel() {
    __shared__ int hist[NBINS];            // 16 KB
    __shared__ int segs[256];
    __shared__ int warpTot[8];
    __shared__ float s_thr;
    __shared__ int s_cnt;

    const int row = blockIdx.x;
    const int t = threadIdx.x;
    const int lane = t & 31, wid = t >> 5;
    const uint4* p4 = reinterpret_cast<const uint4*>(g_preh + (size_t)row * D_HID);

    if (t == 0) s_cnt = 0;

    // Histogram with prefilter (only bins >= PREF_BIN, ~0.5% of elements);
    // full-histogram fallback if suffix above prefilter can't cover TOPK.
    for (int attempt = 0; attempt < 2; attempt++) {
        const int pref = (attempt == 0) ? PREF_BIN : 0;
        #pragma unroll
        for (int i = 0; i < NBINS / 256; i++) hist[t + i * 256] = 0;
        __syncthreads();
        #pragma unroll
        for (int i = 0; i < D_HID / 8 / 256; i++) {
            uint4 v = p4[t + i * 256];
            int b;
            b = bin_of_half_bits(v.x & 0xFFFFu); if (b >= pref) atomicAdd(&hist[b], 1);
            b = bin_of_half_bits(v.x >> 16);     if (b >= pref) atomicAdd(&hist[b], 1);
            b = bin_of_half_bits(v.y & 0xFFFFu); if (b >= pref) atomicAdd(&hist[b], 1);
            b = bin_of_half_bits(v.y >> 16);     if (b >= pref) atomicAdd(&hist[b], 1);
            b = bin_of_half_bits(v.z & 0xFFFFu); if (b >= pref) atomicAdd(&hist[b], 1);
            b = bin_of_half_bits(v.z >> 16);     if (b >= pref) atomicAdd(&hist[b], 1);
            b = bin_of_half_bits(v.w & 0xFFFFu); if (b >= pref) atomicAdd(&hist[b], 1);
            b = bin_of_half_bits(v.w >> 16);     if (b >= pref) atomicAdd(&hist[b], 1);
        }
        __syncthreads();

        int seg = 0;
        #pragma unroll
        for (int k = 0; k < 16; k++) seg += hist[t * 16 + k];
        segs[t] = seg;
        int wsum = seg;
        #pragma unroll
        for (int o = 16; o > 0; o >>= 1) wsum += __shfl_xor_sync(0xffffffffu, wsum, o);
        if (lane == 0) warpTot[wid] = wsum;
        __syncthreads();
        int total = warpTot[0] + warpTot[1] + warpTot[2] + warpTot[3]
                  + warpTot[4] + warpTot[5] + warpTot[6] + warpTot[7];
        if (total >= TOPK) break;
        __syncthreads();
    }

    if (t == 0) {
        int cum = 0, w = 7;
        for (; w > 0; w--) { if (cum + warpTot[w] >= TOPK) break; cum += warpTot[w]; }
        int s = w * 32 + 31;
        for (; s > w * 32; s--) { if (cum + segs[s] >= TOPK) break; cum += segs[s]; }
        int b = s * 16 + 15;
        for (; b > s * 16; b--) { if (cum + hist[b] >= TOPK) break; cum += hist[b]; }
        uint32_t keyLo = (uint32_t)b << 4;
        uint32_t hbits = (keyLo & 0x8000u) ? (keyLo & 0x7FFFu) : ((~keyLo) & 0xFFFFu);
        __half_raw hr; hr.x = (unsigned short)hbits;
        s_thr = __half2float(__half(hr)) - MARGIN;
    }
    __syncthreads();

    const float thr = s_thr;
    const __half* p = g_preh + (size_t)row * D_HID;
    for (int i = t; i < D_HID; i += 256) {
        if (__half2float(p[i]) >= thr) {
            int pos = atomicAdd(&s_cnt, 1);
            if (pos < CAND_MAX) g_ci[(size_t)row * CAND_MAX + pos] = i;
        }
    }
    __syncthreads();
    if (t == 0) g_cn[row] = (s_cnt < CAND_MAX) ? s_cnt : CAND_MAX;
}

// ---------------- rescue: exact fp32 dots (R1-identical order) + top-128 ------
__global__ __launch_bounds__(256, 2) void rescue_kernel(const float* __restrict__ b_enc) {
    extern __shared__ float dyn[];
    float* sx = dyn;                                   // [D_MODEL]
    float* sw = dyn + D_MODEL;                         // [CAND_MAX][RPAD]
    float* sv = sw + CAND_MAX * RPAD;                  // [CAND_MAX]
    int*   si = (int*)(sv + CAND_MAX);                 // [CAND_MAX]

    const int row = blockIdx.x;
    const int t = threadIdx.x;

    #pragma unroll
    for (int q = 0; q < 4; q++)
        sx[t + q * 256] = g_xn[(size_t)row * D_MODEL + t + q * 256];
    si[t] = (t < g_cn[row]) ? g_ci[(size_t)row * CAND_MAX + t] : 0x7FFFFFFF;
    __syncthreads();
    const int C = g_cn[row];
    const int myIdx = si[t];

    float acc = 0.f;
    for (int k0 = 0; k0 < D_MODEL; k0 += RTILE) {
        const int q = t & 15;                // 16 float4 = 64 floats
        #pragma unroll
        for (int pass = 0; pass < 16; pass++) {
            const int c = pass * 16 + (t >> 4);
            if (c < C) {
                const float4 v = *reinterpret_cast<const float4*>(
                    g_bt + (size_t)si[c] * D_MODEL + k0 + q * 4);
                float* dst = sw + c * RPAD + q * 4;
                dst[0] = v.x; dst[1] = v.y; dst[2] = v.z; dst[3] = v.w;
            }
        }
        __syncthreads();
        if (t < C) {
            const float* wrow = sw + t * RPAD;
            #pragma unroll
            for (int kk = 0; kk < RTILE; kk++)
                acc = fmaf(sx[k0 + kk], wrow[kk], acc);   // strict sequential chain
        }
        __syncthreads();
    }

    if (t < C) {
        sv[t] = acc + __ldg(&b_enc[myIdx]);
    } else {
        sv[t] = -__int_as_float(0x7F800000);   // -inf
    }
    __syncthreads();

    // bitonic sort 256: val desc, idx asc (jax tie order)
    #pragma unroll 1
    for (int k = 2; k <= CAND_MAX; k <<= 1) {
        #pragma unroll 1
        for (int j = k >> 1; j > 0; j >>= 1) {
            const int ixj = t ^ j;
            if (ixj > t) {
                float v0 = sv[t], v1 = sv[ixj];
                int i0 = si[t], i1 = si[ixj];
                bool firstWins = (v0 > v1) || (v0 == v1 && i0 < i1);
                if (((t & k) == 0) != firstWins) {
                    sv[t] = v1; sv[ixj] = v0;
                    si[t] = i1; si[ixj] = i0;
                }
            }
            __syncthreads();
        }
    }

    if (t < TOPK) {
        g_tv[(size_t)row * TOPK + t] = fmaxf(sv[t], 0.0f);
        g_ti[(size_t)row * TOPK + t] = si[t];
    }
}

// ---------------- sparse decode (fp32 weights) + de-normalize -----------------
__global__ __launch_bounds__(256) void decode_kernel(const float* __restrict__ w_dec,
                                                     const float* __restrict__ b_pre,
                                                     float* __restrict__ out) {
    __shared__ float sval[TOPK];
    __shared__ int   sidx[TOPK];
    const int row = blockIdx.x;
    const int t = threadIdx.x;
    if (t < TOPK) {
        sval[t] = g_tv[(size_t)row * TOPK + t];
        sidx[t] = g_ti[(size_t)row * TOPK + t];
    }
    __syncthreads();

    float acc0 = 0.f, acc1 = 0.f, acc2 = 0.f, acc3 = 0.f;
    #pragma unroll 4
    for (int j = 0; j < TOPK; j++) {
        const float v = sval[j];
        const float* wr = w_dec + (size_t)sidx[j] * D_MODEL;
        acc0 += v * __ldg(&wr[t]);
        acc1 += v * __ldg(&wr[t + 256]);
        acc2 += v * __ldg(&wr[t + 512]);
        acc3 += v * __ldg(&wr[t + 768]);
    }
    const float m = g_mu[row], s = g_sd[row];
    float* o = out + (size_t)row * D_MODEL;
    o[t]       = (acc0 + b_pre[t])       * s + m;
    o[t + 256] = (acc1 + b_pre[t + 256]) * s + m;
    o[t + 512] = (acc2 + b_pre[t + 512]) * s + m;
    o[t + 768] = (acc3 + b_pre[t + 768]) * s + m;
}

// ---------------- launch ------------------------------------------------------
extern "C" void kernel_launch(void* const* d_in, const int* in_sizes, int n_in,
                              void* d_out, int out_size) {
    const float* x     = (const float*)d_in[0];
    const float* w_enc = (const float*)d_in[1];
    const float* w_dec = (const float*)d_in[2];
    const float* b_enc = (const float*)d_in[3];
    const float* b_pre = (const float*)d_in[4];
    float* out = (float*)d_out;

    // 1. LayerNorm (fp32 out + packed swizzled fp16 A tiles)
    ln_kernel<<<N_TOK, 256>>>(x, b_pre);

    // 2. Fused transpose + pack: w_enc -> g_bt fp32 + g_bp fp16(x256)
    dim3 tg(D_HID / 32, D_MODEL / 32);
    transpose_pack_kernel<<<tg, dim3(32, 8)>>>(w_enc);

    // 3. HMMA encoder GEMM with cp.async.bulk pipeline
    cudaFuncSetAttribute(enc_gemm_mma, cudaFuncAttributeMaxDynamicSharedMemorySize, GEMM_SMEM);
    dim3 ggrid(N_TOK / TM, D_HID / TN);
    enc_gemm_mma<<<ggrid, 256, GEMM_SMEM>>>(b_enc);

    // 4. Prefiltered histogram-select approx top-128 + margin candidates
    topk_kernel<<<N_TOK, 256>>>();

    // 5. Rescue: R1-identical sequential fp32 dots, smem-staged coalesced loads
    cudaFuncSetAttribute(rescue_kernel, cudaFuncAttributeMaxDynamicSharedMemorySize, RES_SMEM);
    rescue_kernel<<<N_TOK, 256, RES_SMEM>>>(b_enc);

    // 6. Sparse decode (fp32 weights) + un-normalize
    decode_kernel<<<N_TOK, 256>>>(w_dec, b_pre, out);
}

// round 13
// speedup vs baseline: 1.7707x; 1.0003x over previous
#include <cuda_runtime.h>
#include <cuda_fp16.h>
#include <cstdint>

// Problem constants
#define N_TOK   4096
#define D_MODEL 1024
#define D_HID   32768
#define TOPK    128
#define EPS     1e-5f
#define CAND_MAX 256
#define MARGIN  4e-3f
#define NBINS   4096
#define PREF_BIN 2880                    // bin of fp16(+0.25); rows' 128th ~0.47
#define PREF_BITS2 0x34003400u           // packed fp16 bits of +0.25

// GEMM tiling (fp16)
#define TM   128
#define TN   128
#define TKC  64                          // k-halfs per chunk
#define NCHUNK (D_MODEL / TKC)           // 16
#define TILE_BYTES 16384                 // one packed 128x64 fp16 tile
#define STAGE_BYTES 32768                // A tile + B tile
#define GEMM_SMEM (2 * STAGE_BYTES)      // 64 KB

// Rescue tiling
#define RTILE 64
#define RPAD  65
#define RES_SMEM ((D_MODEL + CAND_MAX * RPAD + CAND_MAX + CAND_MAX) * 4)

// ---------------- scratch (device globals; no allocs allowed) ----------------
__device__ float  g_xn[(size_t)N_TOK * D_MODEL];           // xn fp32 (rescue)
__device__ float  g_bt[(size_t)D_HID * D_MODEL];           // w_enc^T fp32 (rescue)
__device__ __align__(128) __half g_ap[(size_t)N_TOK * D_MODEL];   // packed swizzled A
__device__ __align__(128) __half g_bp[(size_t)D_HID * D_MODEL];   // packed swizzled B
__device__ __half g_preh[(size_t)N_TOK * D_HID];           // 256 MB approx pre-acts
__device__ float g_mu[N_TOK];
__device__ float g_sd[N_TOK];
__device__ int   g_ci[(size_t)N_TOK * CAND_MAX];
__device__ int   g_cn[N_TOK];
__device__ float g_tv[(size_t)N_TOK * TOPK];
__device__ int   g_ti[(size_t)N_TOK * TOPK];

// ---------------- PTX helpers -------------------------------------------------
__device__ __forceinline__ uint32_t smem_u32(const void* p) {
    uint32_t a;
    asm("{ .reg .u64 t; cvta.to.shared.u64 t, %1; cvt.u32.u64 %0, t; }" : "=r"(a) : "l"(p));
    return a;
}
#define MBAR_INIT(a, n) asm volatile("mbarrier.init.shared.b64 [%0], %1;" :: "r"(a), "r"(n) : "memory")
#define MBAR_EXPECT(a, bytes) \
    asm volatile("mbarrier.arrive.expect_tx.shared.b64 _, [%0], %1;" :: "r"(a), "r"(bytes) : "memory")
#define MBAR_WAIT(a, ph) do {                                                          \
    uint32_t _m = (a), _p = (ph);                                                      \
    asm volatile("{\n\t.reg .pred P;\n\tWL_%=:\n\t"                                    \
        "mbarrier.try_wait.parity.acquire.cta.shared::cta.b64 P, [%0], %1, 0x989680;\n\t" \
        "@P bra.uni WD_%=;\n\tbra.uni WL_%=;\n\tWD_%=:\n\t}" :: "r"(_m), "r"(_p) : "memory"); \
} while (0)
__device__ __forceinline__ void bulk_cp(uint32_t dst, const void* src, uint32_t bytes, uint32_t mbar) {
    asm volatile(
        "cp.async.bulk.shared::cluster.global.mbarrier::complete_tx::bytes [%0], [%1], %2, [%3];"
        :: "r"(dst), "l"(src), "r"(bytes), "r"(mbar) : "memory");
}

#define LDSM4(R0, R1, R2, R3, A)                                                  \
    asm volatile("ldmatrix.sync.aligned.m8n8.x4.shared.b16 {%0,%1,%2,%3}, [%4];"  \
        : "=r"(R0), "=r"(R1), "=r"(R2), "=r"(R3) : "r"(A))

// fp16-accumulator HMMA: D/C are 2 regs of half2 (potentially 2x f32-acc rate)
#define MMA16816H(D, A, B0, B1)                                                   \
    asm volatile("mma.sync.aligned.m16n8k16.row.col.f16.f16.f16.f16 "             \
        "{%0,%1}, {%2,%3,%4,%5}, {%6,%7}, {%0,%1};"                                \
        : "+r"((D)[0]), "+r"((D)[1])                                               \
        : "r"((A)[0]), "r"((A)[1]), "r"((A)[2]), "r"((A)[3]), "r"(B0), "r"(B1))

// ---------------- LayerNorm + direct packed-A write ---------------------------
__device__ __forceinline__ float block_reduce_sum256(float v, float* red) {
    #pragma unroll
    for (int o = 16; o > 0; o >>= 1) v += __shfl_xor_sync(0xffffffffu, v, o);
    int w = threadIdx.x >> 5;
    if ((threadIdx.x & 31) == 0) red[w] = v;
    __syncthreads();
    float r = (threadIdx.x < 8) ? red[threadIdx.x] : 0.f;
    if (threadIdx.x < 32) {
        #pragma unroll
        for (int o = 4; o > 0; o >>= 1) r += __shfl_xor_sync(0xffffffffu, r, o);
        if (threadIdx.x == 0) red[0] = r;
    }
    __syncthreads();
    float out = red[0];
    __syncthreads();
    return out;
}

__global__ __launch_bounds__(256) void ln_kernel(const float* __restrict__ x,
                                                 const float* __restrict__ b_pre) {
    __shared__ float sx[D_MODEL];
    __shared__ float red[32];
    const int row = blockIdx.x;
    const int t = threadIdx.x;
    const float* xr = x + (size_t)row * D_MODEL;

    float sum = 0.f;
    #pragma unroll
    for (int q = 0; q < 4; q++) { float f = xr[t + q * 256]; sx[t + q * 256] = f; sum += f; }
    float m = block_reduce_sum256(sum, red) * (1.0f / D_MODEL);

    float sq = 0.f;
    #pragma unroll
    for (int q = 0; q < 4; q++) { float c = sx[t + q * 256] - m; sq += c * c; }
    float sd = sqrtf(block_reduce_sum256(sq, red) * (1.0f / (D_MODEL - 1)));
    float inv = 1.0f / (sd + EPS);

    #pragma unroll
    for (int q = 0; q < 4; q++) {
        int col = t + q * 256;
        float v = (sx[col] - m) * inv - b_pre[col];
        g_xn[(size_t)row * D_MODEL + col] = v;
        sx[col] = v;
    }
    if (t == 0) { g_mu[row] = m; g_sd[row] = sd; }
    __syncthreads();

    if (t < 128) {
        const int c = t >> 3;            // k-chunk 0..15
        const int eg = t & 7;            // 16B group within 128B row
        const int k = t * 8;
        __half2 h[4];
        #pragma unroll
        for (int j = 0; j < 4; j++)
            h[j] = __floats2half2_rn(sx[k + 2*j], sx[k + 2*j + 1]);
        const int blk = row >> 7, r = row & 127;
        char* tile = (char*)g_ap + ((size_t)blk * NCHUNK + c) * TILE_BYTES;
        *reinterpret_cast<uint4*>(tile + r * 128 + ((eg ^ (r & 7)) * 16)) =
            *reinterpret_cast<uint4*>(h);
    }
}

// ---------------- fused transpose + pack: w_enc -> g_bt fp32 + g_bp fp16 ------
__global__ __launch_bounds__(256) void transpose_pack_kernel(const float* __restrict__ w) {
    __shared__ float tile[32][33];
    const int n0 = blockIdx.x * 32, k0 = blockIdx.y * 32;
    const int tx = threadIdx.x, ty = threadIdx.y;
    const int t = ty * 32 + tx;
    #pragma unroll
    for (int i = 0; i < 32; i += 8)
        tile[ty + i][tx] = w[(size_t)(k0 + ty + i) * D_HID + n0 + tx];
    __syncthreads();
    #pragma unroll
    for (int i = 0; i < 32; i += 8)
        g_bt[(size_t)(n0 + ty + i) * D_MODEL + k0 + tx] = tile[tx][ty + i];
    if (t < 128) {
        const int r = t >> 2;            // local n row 0..31
        const int gq = t & 3;            // 8-k group 0..3
        const int n = n0 + r;
        const int k = k0 + gq * 8;
        __half2 h[4];
        #pragma unroll
        for (int j = 0; j < 4; j++)
            h[j] = __floats2half2_rn(tile[gq*8 + 2*j][r] * 256.0f,
                                     tile[gq*8 + 2*j + 1][r] * 256.0f);
        const int blk = n >> 7, c = k >> 6;
        const int r128 = n & 127;
        const int eg = (k & 63) >> 3;
        char* tp = (char*)g_bp + ((size_t)blk * NCHUNK + c) * TILE_BYTES;
        *reinterpret_cast<uint4*>(tp + r128 * 128 + ((eg ^ (r128 & 7)) * 16)) =
            *reinterpret_cast<uint4*>(h);
    }
}

// ---------------- HMMA GEMM (fp16 acc): bulk-copy pipeline --------------------
__global__ __launch_bounds__(256, 2) void enc_gemm_mma(const float* __restrict__ bias) {
    extern __shared__ __align__(1024) char smem[];
    const uint32_t sb = smem_u32(smem);
    __shared__ __align__(8) uint64_t mbar_store[2];
    const uint32_t mb0 = smem_u32(&mbar_store[0]);
    const uint32_t mb1 = smem_u32(&mbar_store[1]);

    const int t = threadIdx.x;
    const int wid = t >> 5, lane = t & 31;
    const int wm = wid >> 1, wn = wid & 1;      // 4x2 warps, warp tile 32x64
    const int Mblk = blockIdx.x;
    const int Nblk = blockIdx.y;
    const int bm = Mblk * TM;
    const int bn = Nblk * TN;

    if (t == 0) { MBAR_INIT(mb0, 1); MBAR_INIT(mb1, 1); }
    __syncthreads();

    uint32_t acc[2][8][2];                      // fp16x2 accumulators
    #pragma unroll
    for (int i = 0; i < 2; i++)
        #pragma unroll
        for (int j = 0; j < 8; j++) { acc[i][j][0] = 0u; acc[i][j][1] = 0u; }

    const int laneA = lane & 15;
    const int hiA   = lane >> 4;
    const int rBoff = (lane & 7) + ((lane >> 4) << 3);
    const int hiB   = (lane >> 3) & 1;

    const char* Abase = (const char*)g_ap + (size_t)Mblk * NCHUNK * TILE_BYTES;
    const char* Bbase = (const char*)g_bp + (size_t)Nblk * NCHUNK * TILE_BYTES;

    if (t == 0) {
        MBAR_EXPECT(mb0, STAGE_BYTES);
        bulk_cp(sb,         Abase, TILE_BYTES, mb0);
        bulk_cp(sb + 16384, Bbase, TILE_BYTES, mb0);
    }

    for (int c = 0; c < NCHUNK; c++) {
        const int s = c & 1;
        if (c + 1 < NCHUNK && t == 0) {
            const uint32_t mbN = (s ? mb0 : mb1);
            const uint32_t stN = sb + (uint32_t)(1 - s) * STAGE_BYTES;
            MBAR_EXPECT(mbN, STAGE_BYTES);
            bulk_cp(stN,         Abase + (size_t)(c + 1) * TILE_BYTES, TILE_BYTES, mbN);
            bulk_cp(stN + 16384, Bbase + (size_t)(c + 1) * TILE_BYTES, TILE_BYTES, mbN);
        }
        MBAR_WAIT(s ? mb1 : mb0, (c >> 1) & 1);

        const uint32_t base = sb + (uint32_t)s * STAGE_BYTES;
        const uint32_t Ah = base, Bh = base + 16384;

        #pragma unroll
        for (int ks = 0; ks < 4; ks++) {
            const int c0 = ks * 2;
            uint32_t aH[2][4], bH[8][2];
            #pragma unroll
            for (int tm = 0; tm < 2; tm++) {
                int r = wm * 32 + tm * 16 + laneA;
                uint32_t off = (uint32_t)r * 128 + (uint32_t)((((c0 + hiA) ^ (r & 7))) * 16);
                LDSM4(aH[tm][0], aH[tm][1], aH[tm][2], aH[tm][3], Ah + off);
            }
            #pragma unroll
            for (int tp = 0; tp < 4; tp++) {
                int r = wn * 64 + tp * 16 + rBoff;
                uint32_t off = (uint32_t)r * 128 + (uint32_t)((((c0 + hiB) ^ (r & 7))) * 16);
                LDSM4(bH[2*tp][0], bH[2*tp][1], bH[2*tp+1][0], bH[2*tp+1][1], Bh + off);
            }
            #pragma unroll
            for (int tm = 0; tm < 2; tm++)
                #pragma unroll
                for (int tn = 0; tn < 8; tn++)
                    MMA16816H(acc[tm][tn], aH[tm], bH[tn][0], bH[tn][1]);
        }
        __syncthreads();
    }

    // epilogue: unpack fp16 acc, unscale (B was x256), add bias, store fp16
    const float inv256 = 1.0f / 256.0f;
    const int gid = lane >> 2, tig = lane & 3;
    #pragma unroll
    for (int tm = 0; tm < 2; tm++) {
        const int r0 = bm + wm * 32 + tm * 16 + gid;
        #pragma unroll
        for (int tn = 0; tn < 8; tn++) {
            const int col = bn + wn * 64 + tn * 8 + tig * 2;
            const float b0 = __ldg(&bias[col]);
            const float b1 = __ldg(&bias[col + 1]);
            const float2 f01 = __half22float2(*reinterpret_cast<__half2*>(&acc[tm][tn][0]));
            const float2 f23 = __half22float2(*reinterpret_cast<__half2*>(&acc[tm][tn][1]));
            __half2 h0 = __floats2half2_rn(f01.x * inv256 + b0, f01.y * inv256 + b1);
            __half2 h1 = __floats2half2_rn(f23.x * inv256 + b0, f23.y * inv256 + b1);
            *reinterpret_cast<__half2*>(&g_preh[(size_t)r0 * D_HID + col]) = h0;
            *reinterpret_cast<__half2*>(&g_preh[(size_t)(r0 + 8) * D_HID + col]) = h1;
        }
    }
}

// ---------------- topk: SIMD-prefiltered fp16-key histogram select ------------
__device__ __forceinline__ int bin_of_half_bits(uint32_t h) {
    uint32_t k = (h & 0x8000u) ? ((~h) & 0xFFFFu) : (h | 0x8000u);
    return (int)(k >> 4);
}

__global__ __launch_bounds__(256) void topk_kernel() {
    __shared__ int hist[NBINS];            // 16 KB
    __shared__ int segs[256];
    __shared__ int warpTot[8];
    __shared__ float s_thr;
    __shared__ int s_cnt;

    const int row = blockIdx.x;
    const int t = threadIdx.x;
    const int lane = t & 31, wid = t >> 5;
    const uint4* p4 = reinterpret_cast<const uint4*>(g_preh + (size_t)row * D_HID);

    if (t == 0) s_cnt = 0;

    for (int attempt = 0; attempt < 2; attempt++) {
        #pragma unroll
        for (int i = 0; i < NBINS / 256; i++) hist[t + i * 256] = 0;
        __syncthreads();
        if (attempt == 0) {
            // SIMD prefilter: positive AND >= 0.25 -> bits in [0x3400, 0x8000)
            #pragma unroll
            for (int i = 0; i < D_HID / 8 / 256; i++) {
                const uint4 v = p4[t + i * 256];
                #pragma unroll
                for (int wsel = 0; wsel < 4; wsel++) {
                    const uint32_t w = (&v.x)[wsel];
                    const uint32_t m = __vcmpgeu2(w, PREF_BITS2) & __vcmpltu2(w, 0x80008000u);
                    if (m) {
                        if (m & 0xFFFFu) atomicAdd(&hist[(int)(((w & 0xFFFFu) | 0x8000u) >> 4)], 1);
                        if (m >> 16)     atomicAdd(&hist[(int)(((w >> 16) | 0x8000u) >> 4)], 1);
                    }
                }
            }
        } else {
            // full-histogram fallback (all values, incl. negatives)
            #pragma unroll
            for (int i = 0; i < D_HID / 8 / 256; i++) {
                const uint4 v = p4[t + i * 256];
                #pragma unroll
                for (int wsel = 0; wsel < 4; wsel++) {
                    const uint32_t w = (&v.x)[wsel];
                    atomicAdd(&hist[bin_of_half_bits(w & 0xFFFFu)], 1);
                    atomicAdd(&hist[bin_of_half_bits(w >> 16)], 1);
                }
            }
        }
        __syncthreads();

        int seg = 0;
        #pragma unroll
        for (int k = 0; k < 16; k++) seg += hist[t * 16 + k];
        segs[t] = seg;
        int wsum = seg;
        #pragma unroll
        for (int o = 16; o > 0; o >>= 1) wsum += __shfl_xor_sync(0xffffffffu, wsum, o);
        if (lane == 0) warpTot[wid] = wsum;
        __syncthreads();
        int total = warpTot[0] + warpTot[1] + warpTot[2] + warpTot[3]
                  + warpTot[4] + warpTot[5] + warpTot[6] + warpTot[7];
        if (total >= TOPK) break;
        __syncthreads();
    }

    if (t == 0) {
        int cum = 0, w = 7;
        for (; w > 0; w--) { if (cum + warpTot[w] >= TOPK) break; cum += warpTot[w]; }
        int s = w * 32 + 31;
        for (; s > w * 32; s--) { if (cum + segs[s] >= TOPK) break; cum += segs[s]; }
        int b = s * 16 + 15;
        for (; b > s * 16; b--) { if (cum + hist[b] >= TOPK) break; cum += hist[b]; }
        uint32_t keyLo = (uint32_t)b << 4;
        uint32_t hbits = (keyLo & 0x8000u) ? (keyLo & 0x7FFFu) : ((~keyLo) & 0xFFFFu);
        __half_raw hr; hr.x = (unsigned short)hbits;
        s_thr = __half2float(__half(hr)) - MARGIN;
    }
    __syncthreads();

    const float thr = s_thr;
    if (thr > 0.0f) {
        // integer-domain collection (round-down keeps candidate set a superset)
        const uint16_t tb = __half_as_ushort(__float2half_rd(thr));
        const uint32_t thr2 = (uint32_t)tb | ((uint32_t)tb << 16);
        for (int i = t; i < D_HID / 8; i += 256) {
            const uint4 v = p4[i];
            #pragma unroll
            for (int wsel = 0; wsel < 4; wsel++) {
                const uint32_t w = (&v.x)[wsel];
                const uint32_t m = __vcmpgeu2(w, thr2) & __vcmpltu2(w, 0x80008000u);
                if (m) {
                    const int base = i * 8 + wsel * 2;
                    if (m & 0xFFFFu) {
                        int pos = atomicAdd(&s_cnt, 1);
                        if (pos < CAND_MAX) g_ci[(size_t)row * CAND_MAX + pos] = base;
                    }
                    if (m >> 16) {
                        int pos = atomicAdd(&s_cnt, 1);
                        if (pos < CAND_MAX) g_ci[(size_t)row * CAND_MAX + pos] = base + 1;
                    }
                }
            }
        }
    } else {
        const __half* p = g_preh + (size_t)row * D_HID;
        for (int i = t; i < D_HID; i += 256) {
            if (__half2float(p[i]) >= thr) {
                int pos = atomicAdd(&s_cnt, 1);
                if (pos < CAND_MAX) g_ci[(size_t)row * CAND_MAX + pos] = i;
            }
        }
    }
    __syncthreads();
    if (t == 0) g_cn[row] = (s_cnt < CAND_MAX) ? s_cnt : CAND_MAX;
}

// ---------------- rescue: exact fp32 dots (R1-identical order) + top-128 ------
__global__ __launch_bounds__(256, 2) void rescue_kernel(const float* __restrict__ b_enc) {
    extern __shared__ float dyn[];
    float* sx = dyn;                                   // [D_MODEL]
    float* sw = dyn + D_MODEL;                         // [CAND_MAX][RPAD]
    float* sv = sw + CAND_MAX * RPAD;                  // [CAND_MAX]
    int*   si = (int*)(sv + CAND_MAX);                 // [CAND_MAX]

    const int row = blockIdx.x;
    const int t = threadIdx.x;

    #pragma unroll
    for (int q = 0; q < 4; q++)
        sx[t + q * 256] = g_xn[(size_t)row * D_MODEL + t + q * 256];
    si[t] = (t < g_cn[row]) ? g_ci[(size_t)row * CAND_MAX + t] : 0x7FFFFFFF;
    __syncthreads();
    const int C = g_cn[row];
    const int myIdx = si[t];

    float acc = 0.f;
    for (int k0 = 0; k0 < D_MODEL; k0 += RTILE) {
        const int q = t & 15;                // 16 float4 = 64 floats
        #pragma unroll
        for (int pass = 0; pass < 16; pass++) {
            const int c = pass * 16 + (t >> 4);
            if (c < C) {
                const float4 v = *reinterpret_cast<const float4*>(
                    g_bt + (size_t)si[c] * D_MODEL + k0 + q * 4);
                float* dst = sw + c * RPAD + q * 4;
                dst[0] = v.x; dst[1] = v.y; dst[2] = v.z; dst[3] = v.w;
            }
        }
        __syncthreads();
        if (t < C) {
            const float* wrow = sw + t * RPAD;
            #pragma unroll
            for (int kk = 0; kk < RTILE; kk++)
                acc = fmaf(sx[k0 + kk], wrow[kk], acc);   // strict sequential chain
        }
        __syncthreads();
    }

    if (t < C) {
        sv[t] = acc + __ldg(&b_enc[myIdx]);
    } else {
        sv[t] = -__int_as_float(0x7F800000);   // -inf
    }
    __syncthreads();

    // bitonic sort 256: val desc, idx asc (jax tie order)
    #pragma unroll 1
    for (int k = 2; k <= CAND_MAX; k <<= 1) {
        #pragma unroll 1
        for (int j = k >> 1; j > 0; j >>= 1) {
            const int ixj = t ^ j;
            if (ixj > t) {
                float v0 = sv[t], v1 = sv[ixj];
                int i0 = si[t], i1 = si[ixj];
                bool firstWins = (v0 > v1) || (v0 == v1 && i0 < i1);
                if (((t & k) == 0) != firstWins) {
                    sv[t] = v1; sv[ixj] = v0;
                    si[t] = i1; si[ixj] = i0;
                }
            }
            __syncthreads();
        }
    }

    if (t < TOPK) {
        g_tv[(size_t)row * TOPK + t] = fmaxf(sv[t], 0.0f);
        g_ti[(size_t)row * TOPK + t] = si[t];
    }
}

// ---------------- sparse decode (fp32 weights) + de-normalize -----------------
__global__ __launch_bounds__(256) void decode_kernel(const float* __restrict__ w_dec,
                                                     const float* __restrict__ b_pre,
                                                     float* __restrict__ out) {
    __shared__ float sval[TOPK];
    __shared__ int   sidx[TOPK];
    const int row = blockIdx.x;
    const int t = threadIdx.x;
    if (t < TOPK) {
        sval[t] = g_tv[(size_t)row * TOPK + t];
        sidx[t] = g_ti[(size_t)row * TOPK + t];
    }
    __syncthreads();

    float acc0 = 0.f, acc1 = 0.f, acc2 = 0.f, acc3 = 0.f;
    #pragma unroll 4
    for (int j = 0; j < TOPK; j++) {
        const float v = sval[j];
        const float* wr = w_dec + (size_t)sidx[j] * D_MODEL;
        acc0 += v * __ldg(&wr[t]);
        acc1 += v * __ldg(&wr[t + 256]);
        acc2 += v * __ldg(&wr[t + 512]);
        acc3 += v * __ldg(&wr[t + 768]);
    }
    const float m = g_mu[row], s = g_sd[row];
    float* o = out + (size_t)row * D_MODEL;
    o[t]       = (acc0 + b_pre[t])       * s + m;
    o[t + 256] = (acc1 + b_pre[t + 256]) * s + m;
    o[t + 512] = (acc2 + b_pre[t + 512]) * s + m;
    o[t + 768] = (acc3 + b_pre[t + 768]) * s + m;
}

// ---------------- launch ------------------------------------------------------
extern "C" void kernel_launch(void* const* d_in, const int* in_sizes, int n_in,
                              void* d_out, int out_size) {
    const float* x     = (const float*)d_in[0];
    const float* w_enc = (const float*)d_in[1];
    const float* w_dec = (const float*)d_in[2];
    const float* b_enc = (const float*)d_in[3];
    const float* b_pre = (const float*)d_in[4];
    float* out = (float*)d_out;

    // 1. LayerNorm (fp32 out + packed swizzled fp16 A tiles)
    ln_kernel<<<N_TOK, 256>>>(x, b_pre);

    // 2. Fused transpose + pack: w_enc -> g_bt fp32 + g_bp fp16(x256)
    dim3 tg(D_HID / 32, D_MODEL / 32);
    transpose_pack_kernel<<<tg, dim3(32, 8)>>>(w_enc);

    // 3. HMMA encoder GEMM (fp16 acc) with cp.async.bulk pipeline
    cudaFuncSetAttribute(enc_gemm_mma, cudaFuncAttributeMaxDynamicSharedMemorySize, GEMM_SMEM);
    dim3 ggrid(N_TOK / TM, D_HID / TN);
    enc_gemm_mma<<<ggrid, 256, GEMM_SMEM>>>(b_enc);

    // 4. SIMD-prefiltered histogram-select approx top-128 + margin candidates
    topk_kernel<<<N_TOK, 256>>>();

    // 5. Rescue: R1-identical sequential fp32 dots, smem-staged coalesced loads
    cudaFuncSetAttribute(rescue_kernel, cudaFuncAttributeMaxDynamicSharedMemorySize, RES_SMEM);
    rescue_kernel<<<N_TOK, 256, RES_SMEM>>>(b_enc);

    // 6. Sparse decode (fp32 weights) + un-normalize
    decode_kernel<<<N_TOK, 256>>>(w_dec, b_pre, out);
}

// round 14
// speedup vs baseline: 1.8423x; 1.0405x over previous
#include <cuda_runtime.h>
#include <cuda_fp16.h>
#include <cstdint>

// Problem constants
#define N_TOK   4096
#define D_MODEL 1024
#define D_HID   32768
#define TOPK    128
#define EPS     1e-5f
#define CAND_MAX 256
#define MARGIN  4e-3f
#define NBINS   4096
#define FLOOR   0.30f                    // fixed list floor; rows' 128th ~0.47
#define LIST_CAP 2048

// GEMM tiling (fp16)
#define TM   128
#define TN   128
#define TKC  64                          // k-halfs per chunk
#define NCHUNK (D_MODEL / TKC)           // 16
#define TILE_BYTES 16384                 // one packed 128x64 fp16 tile
#define STAGE_BYTES 32768                // A tile + B tile
#define GEMM_SMEM (2 * STAGE_BYTES)      // 64 KB

// Rescue tiling
#define RTILE 64
#define RPAD  65
#define RES_SMEM ((D_MODEL + CAND_MAX * RPAD + CAND_MAX + CAND_MAX) * 4)

// ---------------- scratch (device globals; no allocs allowed) ----------------
__device__ float  g_xn[(size_t)N_TOK * D_MODEL];           // xn fp32 (rescue)
__device__ float  g_bt[(size_t)D_HID * D_MODEL];           // w_enc^T fp32 (rescue)
__device__ __align__(128) __half g_ap[(size_t)N_TOK * D_MODEL];   // packed swizzled A
__device__ __align__(128) __half g_bp[(size_t)D_HID * D_MODEL];   // packed swizzled B
__device__ __half g_wd[(size_t)D_HID * D_MODEL];           // w_dec fp16 (decode)
__device__ __half g_preh[(size_t)N_TOK * D_HID];           // pre-acts (fallback only)
__device__ uint32_t g_list[(size_t)N_TOK * LIST_CAP];      // (val16<<16)|idx per row
__device__ int   g_ln[N_TOK];                              // list counts
__device__ float g_mu[N_TOK];
__device__ float g_sd[N_TOK];
__device__ int   g_ci[(size_t)N_TOK * CAND_MAX];
__device__ int   g_cn[N_TOK];
__device__ float g_tv[(size_t)N_TOK * TOPK];
__device__ int   g_ti[(size_t)N_TOK * TOPK];

// ---------------- PTX helpers -------------------------------------------------
__device__ __forceinline__ uint32_t smem_u32(const void* p) {
    uint32_t a;
    asm("{ .reg .u64 t; cvta.to.shared.u64 t, %1; cvt.u32.u64 %0, t; }" : "=r"(a) : "l"(p));
    return a;
}
#define MBAR_INIT(a, n) asm volatile("mbarrier.init.shared.b64 [%0], %1;" :: "r"(a), "r"(n) : "memory")
#define MBAR_EXPECT(a, bytes) \
    asm volatile("mbarrier.arrive.expect_tx.shared.b64 _, [%0], %1;" :: "r"(a), "r"(bytes) : "memory")
#define MBAR_WAIT(a, ph) do {                                                          \
    uint32_t _m = (a), _p = (ph);                                                      \
    asm volatile("{\n\t.reg .pred P;\n\tWL_%=:\n\t"                                    \
        "mbarrier.try_wait.parity.acquire.cta.shared::cta.b64 P, [%0], %1, 0x989680;\n\t" \
        "@P bra.uni WD_%=;\n\tbra.uni WL_%=;\n\tWD_%=:\n\t}" :: "r"(_m), "r"(_p) : "memory"); \
} while (0)
__device__ __forceinline__ void bulk_cp(uint32_t dst, const void* src, uint32_t bytes, uint32_t mbar) {
    asm volatile(
        "cp.async.bulk.shared::cluster.global.mbarrier::complete_tx::bytes [%0], [%1], %2, [%3];"
        :: "r"(dst), "l"(src), "r"(bytes), "r"(mbar) : "memory");
}

#define LDSM4(R0, R1, R2, R3, A)                                                  \
    asm volatile("ldmatrix.sync.aligned.m8n8.x4.shared.b16 {%0,%1,%2,%3}, [%4];"  \
        : "=r"(R0), "=r"(R1), "=r"(R2), "=r"(R3) : "r"(A))

#define MMA16816(D, A, B0, B1)                                                    \
    asm volatile("mma.sync.aligned.m16n8k16.row.col.f32.f16.f16.f32 "             \
        "{%0,%1,%2,%3}, {%4,%5,%6,%7}, {%8,%9}, {%0,%1,%2,%3};"                   \
        : "+f"((D)[0]), "+f"((D)[1]), "+f"((D)[2]), "+f"((D)[3])                   \
        : "r"((A)[0]), "r"((A)[1]), "r"((A)[2]), "r"((A)[3]), "r"(B0), "r"(B1))

// ---------------- LayerNorm + direct packed-A write ---------------------------
__device__ __forceinline__ float block_reduce_sum256(float v, float* red) {
    #pragma unroll
    for (int o = 16; o > 0; o >>= 1) v += __shfl_xor_sync(0xffffffffu, v, o);
    int w = threadIdx.x >> 5;
    if ((threadIdx.x & 31) == 0) red[w] = v;
    __syncthreads();
    float r = (threadIdx.x < 8) ? red[threadIdx.x] : 0.f;
    if (threadIdx.x < 32) {
        #pragma unroll
        for (int o = 4; o > 0; o >>= 1) r += __shfl_xor_sync(0xffffffffu, r, o);
        if (threadIdx.x == 0) red[0] = r;
    }
    __syncthreads();
    float out = red[0];
    __syncthreads();
    return out;
}

__global__ __launch_bounds__(256) void ln_kernel(const float* __restrict__ x,
                                                 const float* __restrict__ b_pre) {
    __shared__ float sx[D_MODEL];
    __shared__ float red[32];
    const int row = blockIdx.x;
    const int t = threadIdx.x;
    const float* xr = x + (size_t)row * D_MODEL;

    float sum = 0.f;
    #pragma unroll
    for (int q = 0; q < 4; q++) { float f = xr[t + q * 256]; sx[t + q * 256] = f; sum += f; }
    float m = block_reduce_sum256(sum, red) * (1.0f / D_MODEL);

    float sq = 0.f;
    #pragma unroll
    for (int q = 0; q < 4; q++) { float c = sx[t + q * 256] - m; sq += c * c; }
    float sd = sqrtf(block_reduce_sum256(sq, red) * (1.0f / (D_MODEL - 1)));
    float inv = 1.0f / (sd + EPS);

    #pragma unroll
    for (int q = 0; q < 4; q++) {
        int col = t + q * 256;
        float v = (sx[col] - m) * inv - b_pre[col];
        g_xn[(size_t)row * D_MODEL + col] = v;
        sx[col] = v;
    }
    if (t == 0) { g_mu[row] = m; g_sd[row] = sd; g_ln[row] = 0; }   // zero list count
    __syncthreads();

    if (t < 128) {
        const int c = t >> 3;            // k-chunk 0..15
        const int eg = t & 7;            // 16B group within 128B row
        const int k = t * 8;
        __half2 h[4];
        #pragma unroll
        for (int j = 0; j < 4; j++)
            h[j] = __floats2half2_rn(sx[k + 2*j], sx[k + 2*j + 1]);
        const int blk = row >> 7, r = row & 127;
        char* tile = (char*)g_ap + ((size_t)blk * NCHUNK + c) * TILE_BYTES;
        *reinterpret_cast<uint4*>(tile + r * 128 + ((eg ^ (r & 7)) * 16)) =
            *reinterpret_cast<uint4*>(h);
    }
}

// ---------------- fused transpose + pack: w_enc -> g_bt fp32 + g_bp fp16 ------
__global__ __launch_bounds__(256) void transpose_pack_kernel(const float* __restrict__ w) {
    __shared__ float tile[32][33];
    const int n0 = blockIdx.x * 32, k0 = blockIdx.y * 32;
    const int tx = threadIdx.x, ty = threadIdx.y;
    const int t = ty * 32 + tx;
    #pragma unroll
    for (int i = 0; i < 32; i += 8)
        tile[ty + i][tx] = w[(size_t)(k0 + ty + i) * D_HID + n0 + tx];
    __syncthreads();
    #pragma unroll
    for (int i = 0; i < 32; i += 8)
        g_bt[(size_t)(n0 + ty + i) * D_MODEL + k0 + tx] = tile[tx][ty + i];
    if (t < 128) {
        const int r = t >> 2;            // local n row 0..31
        const int gq = t & 3;            // 8-k group 0..3
        const int n = n0 + r;
        const int k = k0 + gq * 8;
        __half2 h[4];
        #pragma unroll
        for (int j = 0; j < 4; j++)
            h[j] = __floats2half2_rn(tile[gq*8 + 2*j][r] * 256.0f,
                                     tile[gq*8 + 2*j + 1][r] * 256.0f);
        const int blk = n >> 7, c = k >> 6;
        const int r128 = n & 127;
        const int eg = (k & 63) >> 3;
        char* tp = (char*)g_bp + ((size_t)blk * NCHUNK + c) * TILE_BYTES;
        *reinterpret_cast<uint4*>(tp + r128 * 128 + ((eg ^ (r128 & 7)) * 16)) =
            *reinterpret_cast<uint4*>(h);
    }
}

// ---------------- pack w_dec -> fp16 (decode values only) ---------------------
__global__ __launch_bounds__(256) void wd_pack_kernel(const float* __restrict__ wd) {
    const size_t i = ((size_t)blockIdx.x * 256 + threadIdx.x) * 8;
    const float4 a = *reinterpret_cast<const float4*>(wd + i);
    const float4 b = *reinterpret_cast<const float4*>(wd + i + 4);
    __half2 h[4];
    h[0] = __floats2half2_rn(a.x, a.y);
    h[1] = __floats2half2_rn(a.z, a.w);
    h[2] = __floats2half2_rn(b.x, b.y);
    h[3] = __floats2half2_rn(b.z, b.w);
    *reinterpret_cast<uint4*>(g_wd + i) = *reinterpret_cast<uint4*>(h);
}

// ---------------- HMMA GEMM (f32 acc) + fused candidate extraction ------------
__device__ __forceinline__ void list_push(int row, int col, float f) {
    if (f >= FLOOR) {
        int pos = atomicAdd(&g_ln[row], 1);
        if (pos < LIST_CAP)
            g_list[(size_t)row * LIST_CAP + pos] =
                ((uint32_t)__half_as_ushort(__float2half_rn(f)) << 16) | (uint32_t)col;
    }
}

__global__ __launch_bounds__(256, 2) void enc_gemm_mma(const float* __restrict__ bias) {
    extern __shared__ __align__(1024) char smem[];
    const uint32_t sb = smem_u32(smem);
    __shared__ __align__(8) uint64_t mbar_store[2];
    const uint32_t mb0 = smem_u32(&mbar_store[0]);
    const uint32_t mb1 = smem_u32(&mbar_store[1]);

    const int t = threadIdx.x;
    const int wid = t >> 5, lane = t & 31;
    const int wm = wid >> 1, wn = wid & 1;      // 4x2 warps, warp tile 32x64
    const int Mblk = blockIdx.x;
    const int Nblk = blockIdx.y;
    const int bm = Mblk * TM;
    const int bn = Nblk * TN;

    if (t == 0) { MBAR_INIT(mb0, 1); MBAR_INIT(mb1, 1); }
    __syncthreads();

    float acc[2][8][4];
    #pragma unroll
    for (int i = 0; i < 2; i++)
        #pragma unroll
        for (int j = 0; j < 8; j++)
            #pragma unroll
            for (int q = 0; q < 4; q++) acc[i][j][q] = 0.f;

    const int laneA = lane & 15;
    const int hiA   = lane >> 4;
    const int rBoff = (lane & 7) + ((lane >> 4) << 3);
    const int hiB   = (lane >> 3) & 1;

    const char* Abase = (const char*)g_ap + (size_t)Mblk * NCHUNK * TILE_BYTES;
    const char* Bbase = (const char*)g_bp + (size_t)Nblk * NCHUNK * TILE_BYTES;

    if (t == 0) {
        MBAR_EXPECT(mb0, STAGE_BYTES);
        bulk_cp(sb,         Abase, TILE_BYTES, mb0);
        bulk_cp(sb + 16384, Bbase, TILE_BYTES, mb0);
    }

    for (int c = 0; c < NCHUNK; c++) {
        const int s = c & 1;
        if (c + 1 < NCHUNK && t == 0) {
            const uint32_t mbN = (s ? mb0 : mb1);
            const uint32_t stN = sb + (uint32_t)(1 - s) * STAGE_BYTES;
            MBAR_EXPECT(mbN, STAGE_BYTES);
            bulk_cp(stN,         Abase + (size_t)(c + 1) * TILE_BYTES, TILE_BYTES, mbN);
            bulk_cp(stN + 16384, Bbase + (size_t)(c + 1) * TILE_BYTES, TILE_BYTES, mbN);
        }
        MBAR_WAIT(s ? mb1 : mb0, (c >> 1) & 1);

        const uint32_t base = sb + (uint32_t)s * STAGE_BYTES;
        const uint32_t Ah = base, Bh = base + 16384;

        #pragma unroll
        for (int ks = 0; ks < 4; ks++) {
            const int c0 = ks * 2;
            uint32_t aH[2][4], bH[8][2];
            #pragma unroll
            for (int tm = 0; tm < 2; tm++) {
                int r = wm * 32 + tm * 16 + laneA;
                uint32_t off = (uint32_t)r * 128 + (uint32_t)((((c0 + hiA) ^ (r & 7))) * 16);
                LDSM4(aH[tm][0], aH[tm][1], aH[tm][2], aH[tm][3], Ah + off);
            }
            #pragma unroll
            for (int tp = 0; tp < 4; tp++) {
                int r = wn * 64 + tp * 16 + rBoff;
                uint32_t off = (uint32_t)r * 128 + (uint32_t)((((c0 + hiB) ^ (r & 7))) * 16);
                LDSM4(bH[2*tp][0], bH[2*tp][1], bH[2*tp+1][0], bH[2*tp+1][1], Bh + off);
            }
            #pragma unroll
            for (int tm = 0; tm < 2; tm++)
                #pragma unroll
                for (int tn = 0; tn < 8; tn++)
                    MMA16816(acc[tm][tn], aH[tm], bH[tn][0], bH[tn][1]);
        }
        __syncthreads();
    }

    // epilogue: unscale (B was x256), add bias, store fp16, push candidates
    const float inv256 = 1.0f / 256.0f;
    const int gid = lane >> 2, tig = lane & 3;
    #pragma unroll
    for (int tm = 0; tm < 2; tm++) {
        const int r0 = bm + wm * 32 + tm * 16 + gid;
        #pragma unroll
        for (int tn = 0; tn < 8; tn++) {
            const int col = bn + wn * 64 + tn * 8 + tig * 2;
            const float b0 = __ldg(&bias[col]);
            const float b1 = __ldg(&bias[col + 1]);
            const float f0 = acc[tm][tn][0] * inv256 + b0;
            const float f1 = acc[tm][tn][1] * inv256 + b1;
            const float f2 = acc[tm][tn][2] * inv256 + b0;
            const float f3 = acc[tm][tn][3] * inv256 + b1;
            *reinterpret_cast<__half2*>(&g_preh[(size_t)r0 * D_HID + col]) =
                __floats2half2_rn(f0, f1);
            *reinterpret_cast<__half2*>(&g_preh[(size_t)(r0 + 8) * D_HID + col]) =
                __floats2half2_rn(f2, f3);
            list_push(r0,     col,     f0);
            list_push(r0,     col + 1, f1);
            list_push(r0 + 8, col,     f2);
            list_push(r0 + 8, col + 1, f3);
        }
    }
}

// ---------------- topk: list-based histogram select (fallback: full row) ------
__device__ __forceinline__ int bin_of_half_bits(uint32_t h) {
    uint32_t k = (h & 0x8000u) ? ((~h) & 0xFFFFu) : (h | 0x8000u);
    return (int)(k >> 4);
}

__global__ __launch_bounds__(256) void topk_kernel() {
    __shared__ int hist[NBINS];            // 16 KB
    __shared__ int segs[256];
    __shared__ int warpTot[8];
    __shared__ float s_thr;
    __shared__ int s_cnt;

    const int row = blockIdx.x;
    const int t = threadIdx.x;
    const int lane = t & 31, wid = t >> 5;
    const int n_raw = g_ln[row];
    const bool listOK = (n_raw >= TOPK && n_raw <= LIST_CAP);
    const uint32_t* L = g_list + (size_t)row * LIST_CAP;

    if (t == 0) s_cnt = 0;
    #pragma unroll
    for (int i = 0; i < NBINS / 256; i++) hist[t + i * 256] = 0;
    __syncthreads();

    if (listOK) {
        for (int i = t; i < n_raw; i += 256)
            atomicAdd(&hist[(int)((L[i] | 0x80000000u) >> 20)], 1);
    } else {
        const uint4* p4 = reinterpret_cast<const uint4*>(g_preh + (size_t)row * D_HID);
        #pragma unroll
        for (int i = 0; i < D_HID / 8 / 256; i++) {
            const uint4 v = p4[t + i * 256];
            #pragma unroll
            for (int wsel = 0; wsel < 4; wsel++) {
                const uint32_t w = (&v.x)[wsel];
                atomicAdd(&hist[bin_of_half_bits(w & 0xFFFFu)], 1);
                atomicAdd(&hist[bin_of_half_bits(w >> 16)], 1);
            }
        }
    }
    __syncthreads();

    int seg = 0;
    #pragma unroll
    for (int k = 0; k < 16; k++) seg += hist[t * 16 + k];
    segs[t] = seg;
    int wsum = seg;
    #pragma unroll
    for (int o = 16; o > 0; o >>= 1) wsum += __shfl_xor_sync(0xffffffffu, wsum, o);
    if (lane == 0) warpTot[wid] = wsum;
    __syncthreads();

    if (t == 0) {
        int cum = 0, w = 7;
        for (; w > 0; w--) { if (cum + warpTot[w] >= TOPK) break; cum += warpTot[w]; }
        int s = w * 32 + 31;
        for (; s > w * 32; s--) { if (cum + segs[s] >= TOPK) break; cum += segs[s]; }
        int b = s * 16 + 15;
        for (; b > s * 16; b--) { if (cum + hist[b] >= TOPK) break; cum += hist[b]; }
        uint32_t keyLo = (uint32_t)b << 4;
        uint32_t hbits = (keyLo & 0x8000u) ? (keyLo & 0x7FFFu) : ((~keyLo) & 0xFFFFu);
        __half_raw hr; hr.x = (unsigned short)hbits;
        s_thr = __half2float(__half(hr)) - MARGIN;
    }
    __syncthreads();

    const float thr = s_thr;
    if (listOK && thr >= FLOOR + 0.002f) {
        // collect from list: {x >= thr} is a subset of {x >= FLOOR} = list
        for (int i = t; i < n_raw; i += 256) {
            const uint32_t e = L[i];
            __half_raw hr; hr.x = (unsigned short)(e >> 16);
            if (__half2float(__half(hr)) >= thr) {
                int pos = atomicAdd(&s_cnt, 1);
                if (pos < CAND_MAX) g_ci[(size_t)row * CAND_MAX + pos] = (int)(e & 0xFFFFu);
            }
        }
    } else {
        const __half* p = g_preh + (size_t)row * D_HID;
        for (int i = t; i < D_HID; i += 256) {
            if (__half2float(p[i]) >= thr) {
                int pos = atomicAdd(&s_cnt, 1);
                if (pos < CAND_MAX) g_ci[(size_t)row * CAND_MAX + pos] = i;
            }
        }
    }
    __syncthreads();
    if (t == 0) g_cn[row] = (s_cnt < CAND_MAX) ? s_cnt : CAND_MAX;
}

// ---------------- rescue: exact fp32 dots (R1-identical order) + top-128 ------
__global__ __launch_bounds__(256, 2) void rescue_kernel(const float* __restrict__ b_enc) {
    extern __shared__ float dyn[];
    float* sx = dyn;                                   // [D_MODEL]
    float* sw = dyn + D_MODEL;                         // [CAND_MAX][RPAD]
    float* sv = sw + CAND_MAX * RPAD;                  // [CAND_MAX]
    int*   si = (int*)(sv + CAND_MAX);                 // [CAND_MAX]

    const int row = blockIdx.x;
    const int t = threadIdx.x;

    #pragma unroll
    for (int q = 0; q < 4; q++)
        sx[t + q * 256] = g_xn[(size_t)row * D_MODEL + t + q * 256];
    si[t] = (t < g_cn[row]) ? g_ci[(size_t)row * CAND_MAX + t] : 0x7FFFFFFF;
    __syncthreads();
    const int C = g_cn[row];
    const int myIdx = si[t];

    float acc = 0.f;
    for (int k0 = 0; k0 < D_MODEL; k0 += RTILE) {
        const int q = t & 15;                // 16 float4 = 64 floats
        #pragma unroll
        for (int pass = 0; pass < 16; pass++) {
            const int c = pass * 16 + (t >> 4);
            if (c < C) {
                const float4 v = *reinterpret_cast<const float4*>(
                    g_bt + (size_t)si[c] * D_MODEL + k0 + q * 4);
                float* dst = sw + c * RPAD + q * 4;
                dst[0] = v.x; dst[1] = v.y; dst[2] = v.z; dst[3] = v.w;
            }
        }
        __syncthreads();
        if (t < C) {
            const float* wrow = sw + t * RPAD;
            #pragma unroll
            for (int kk = 0; kk < RTILE; kk++)
                acc = fmaf(sx[k0 + kk], wrow[kk], acc);   // strict sequential chain
        }
        __syncthreads();
    }

    if (t < C) {
        sv[t] = acc + __ldg(&b_enc[myIdx]);
    } else {
        sv[t] = -__int_as_float(0x7F800000);   // -inf
    }
    __syncthreads();

    // bitonic sort 256: val desc, idx asc (jax tie order)
    #pragma unroll 1
    for (int k = 2; k <= CAND_MAX; k <<= 1) {
        #pragma unroll 1
        for (int j = k >> 1; j > 0; j >>= 1) {
            const int ixj = t ^ j;
            if (ixj > t) {
                float v0 = sv[t], v1 = sv[ixj];
                int i0 = si[t], i1 = si[ixj];
                bool firstWins = (v0 > v1) || (v0 == v1 && i0 < i1);
                if (((t & k) == 0) != firstWins) {
                    sv[t] = v1; sv[ixj] = v0;
                    si[t] = i1; si[ixj] = i0;
                }
            }
            __syncthreads();
        }
    }

    if (t < TOPK) {
        g_tv[(size_t)row * TOPK + t] = fmaxf(sv[t], 0.0f);
        g_ti[(size_t)row * TOPK + t] = si[t];
    }
}

// ---------------- sparse decode (fp16 weights) + de-normalize -----------------
__global__ __launch_bounds__(256) void decode_kernel(const float* __restrict__ b_pre,
                                                     float* __restrict__ out) {
    __shared__ float sval[TOPK];
    __shared__ int   sidx[TOPK];
    const int row = blockIdx.x;
    const int t = threadIdx.x;
    if (t < TOPK) {
        sval[t] = g_tv[(size_t)row * TOPK + t];
        sidx[t] = g_ti[(size_t)row * TOPK + t];
    }
    __syncthreads();

    float2 a0 = {0.f, 0.f}, a1 = {0.f, 0.f};
    #pragma unroll 4
    for (int j = 0; j < TOPK; j++) {
        const float v = sval[j];
        const __half2* wr2 = reinterpret_cast<const __half2*>(
            g_wd + (size_t)sidx[j] * D_MODEL);
        const float2 f0 = __half22float2(__ldg(&wr2[t]));
        const float2 f1 = __half22float2(__ldg(&wr2[t + 256]));
        a0.x = fmaf(v, f0.x, a0.x); a0.y = fmaf(v, f0.y, a0.y);
        a1.x = fmaf(v, f1.x, a1.x); a1.y = fmaf(v, f1.y, a1.y);
    }
    const float m = g_mu[row], s = g_sd[row];
    float* o = out + (size_t)row * D_MODEL;
    const int c0 = 2 * t, c1 = 2 * t + 512;
    o[c0]     = (a0.x + b_pre[c0])     * s + m;
    o[c0 + 1] = (a0.y + b_pre[c0 + 1]) * s + m;
    o[c1]     = (a1.x + b_pre[c1])     * s + m;
    o[c1 + 1] = (a1.y + b_pre[c1 + 1]) * s + m;
}

// ---------------- launch ------------------------------------------------------
extern "C" void kernel_launch(void* const* d_in, const int* in_sizes, int n_in,
                              void* d_out, int out_size) {
    const float* x     = (const float*)d_in[0];
    const float* w_enc = (const float*)d_in[1];
    const float* w_dec = (const float*)d_in[2];
    const float* b_enc = (const float*)d_in[3];
    const float* b_pre = (const float*)d_in[4];
    float* out = (float*)d_out;

    // 1. LayerNorm (fp32 out + packed swizzled fp16 A tiles + list-count reset)
    ln_kernel<<<N_TOK, 256>>>(x, b_pre);

    // 2. Fused transpose + pack: w_enc -> g_bt fp32 + g_bp fp16(x256)
    dim3 tg(D_HID / 32, D_MODEL / 32);
    transpose_pack_kernel<<<tg, dim3(32, 8)>>>(w_enc);

    // 3. Pack w_dec -> fp16 (decode values only; selection path untouched)
    wd_pack_kernel<<<(int)(((size_t)D_HID * D_MODEL) / 8 / 256), 256>>>(w_dec);

    // 4. HMMA encoder GEMM (f32 acc) + fused candidate-list extraction
    cudaFuncSetAttribute(enc_gemm_mma, cudaFuncAttributeMaxDynamicSharedMemorySize, GEMM_SMEM);
    dim3 ggrid(N_TOK / TM, D_HID / TN);
    enc_gemm_mma<<<ggrid, 256, GEMM_SMEM>>>(b_enc);

    // 5. List-based histogram select (full-row fallback for safety)
    topk_kernel<<<N_TOK, 256>>>();

    // 6. Rescue: R1-identical sequential fp32 dots, smem-staged coalesced loads
    cudaFuncSetAttribute(rescue_kernel, cudaFuncAttributeMaxDynamicSharedMemorySize, RES_SMEM);
    rescue_kernel<<<N_TOK, 256, RES_SMEM>>>(b_enc);

    // 7. Sparse decode (fp16 weights) + un-normalize
    decode_kernel<<<N_TOK, 256>>>(b_pre, out);
}

// round 15
// speedup vs baseline: 2.4026x; 1.3041x over previous
#include <cuda_runtime.h>
#include <cuda_fp16.h>
#include <cstdint>

// Problem constants
#define N_TOK   4096
#define D_MODEL 1024
#define D_HID   32768
#define TOPK    128
#define EPS     1e-5f
#define CAND_MAX 256
#define MARGIN  4e-3f
#define NBINS   4096
#define FLOOR   0.30f                    // fixed list floor; rows' 128th ~0.47
#define LIST_CAP 2048

// GEMM tiling (fp16)
#define TM   128
#define TN   128
#define TKC  64                          // k-halfs per chunk
#define NCHUNK (D_MODEL / TKC)           // 16
#define TILE_BYTES 16384                 // one packed 128x64 fp16 tile
#define STAGE_BYTES 32768                // A tile + B tile
#define GEMM_SMEM (2 * STAGE_BYTES)      // 64 KB

// Rescue tiling (double-buffered cp.async staging)
#define RTILE 32
#define RPAD  36                         // 144 B row stride (16B-aligned for cp.async)
#define NRTILE (D_MODEL / RTILE)         // 32
#define RES_SMEM ((D_MODEL + 2 * CAND_MAX * RPAD + CAND_MAX + CAND_MAX) * 4)  // ~78 KB

// ---------------- scratch (device globals; no allocs allowed) ----------------
__device__ float  g_xn[(size_t)N_TOK * D_MODEL];           // xn fp32 (rescue)
__device__ float  g_bt[(size_t)D_HID * D_MODEL];           // w_enc^T fp32 (rescue)
__device__ __align__(128) __half g_ap[(size_t)N_TOK * D_MODEL];   // packed swizzled A
__device__ __align__(128) __half g_bp[(size_t)D_HID * D_MODEL];   // packed swizzled B
__device__ __half g_wd[(size_t)D_HID * D_MODEL];           // w_dec fp16 (decode)
__device__ __half g_preh[(size_t)N_TOK * D_HID];           // pre-acts (fallback only)
__device__ uint32_t g_list[(size_t)N_TOK * LIST_CAP];      // (val16<<16)|idx per row
__device__ int   g_ln[N_TOK];                              // list counts
__device__ float g_mu[N_TOK];
__device__ float g_sd[N_TOK];
__device__ int   g_ci[(size_t)N_TOK * CAND_MAX];
__device__ int   g_cn[N_TOK];
__device__ float g_tv[(size_t)N_TOK * TOPK];
__device__ int   g_ti[(size_t)N_TOK * TOPK];

// ---------------- PTX helpers -------------------------------------------------
__device__ __forceinline__ uint32_t smem_u32(const void* p) {
    uint32_t a;
    asm("{ .reg .u64 t; cvta.to.shared.u64 t, %1; cvt.u32.u64 %0, t; }" : "=r"(a) : "l"(p));
    return a;
}
#define MBAR_INIT(a, n) asm volatile("mbarrier.init.shared.b64 [%0], %1;" :: "r"(a), "r"(n) : "memory")
#define MBAR_EXPECT(a, bytes) \
    asm volatile("mbarrier.arrive.expect_tx.shared.b64 _, [%0], %1;" :: "r"(a), "r"(bytes) : "memory")
#define MBAR_WAIT(a, ph) do {                                                          \
    uint32_t _m = (a), _p = (ph);                                                      \
    asm volatile("{\n\t.reg .pred P;\n\tWL_%=:\n\t"                                    \
        "mbarrier.try_wait.parity.acquire.cta.shared::cta.b64 P, [%0], %1, 0x989680;\n\t" \
        "@P bra.uni WD_%=;\n\tbra.uni WL_%=;\n\tWD_%=:\n\t}" :: "r"(_m), "r"(_p) : "memory"); \
} while (0)
__device__ __forceinline__ void bulk_cp(uint32_t dst, const void* src, uint32_t bytes, uint32_t mbar) {
    asm volatile(
        "cp.async.bulk.shared::cluster.global.mbarrier::complete_tx::bytes [%0], [%1], %2, [%3];"
        :: "r"(dst), "l"(src), "r"(bytes), "r"(mbar) : "memory");
}
__device__ __forceinline__ void cp16(uint32_t dst, const void* src) {
    asm volatile("cp.async.cg.shared.global [%0], [%1], 16;" :: "r"(dst), "l"(src) : "memory");
}
#define CP_COMMIT()   asm volatile("cp.async.commit_group;" ::: "memory")
#define CP_WAIT(n)    asm volatile("cp.async.wait_group %0;" :: "n"(n) : "memory")

#define LDSM4(R0, R1, R2, R3, A)                                                  \
    asm volatile("ldmatrix.sync.aligned.m8n8.x4.shared.b16 {%0,%1,%2,%3}, [%4];"  \
        : "=r"(R0), "=r"(R1), "=r"(R2), "=r"(R3) : "r"(A))

#define MMA16816(D, A, B0, B1)                                                    \
    asm volatile("mma.sync.aligned.m16n8k16.row.col.f32.f16.f16.f32 "             \
        "{%0,%1,%2,%3}, {%4,%5,%6,%7}, {%8,%9}, {%0,%1,%2,%3};"                   \
        : "+f"((D)[0]), "+f"((D)[1]), "+f"((D)[2]), "+f"((D)[3])                   \
        : "r"((A)[0]), "r"((A)[1]), "r"((A)[2]), "r"((A)[3]), "r"(B0), "r"(B1))

// ---------------- LayerNorm + direct packed-A write ---------------------------
__device__ __forceinline__ float block_reduce_sum256(float v, float* red) {
    #pragma unroll
    for (int o = 16; o > 0; o >>= 1) v += __shfl_xor_sync(0xffffffffu, v, o);
    int w = threadIdx.x >> 5;
    if ((threadIdx.x & 31) == 0) red[w] = v;
    __syncthreads();
    float r = (threadIdx.x < 8) ? red[threadIdx.x] : 0.f;
    if (threadIdx.x < 32) {
        #pragma unroll
        for (int o = 4; o > 0; o >>= 1) r += __shfl_xor_sync(0xffffffffu, r, o);
        if (threadIdx.x == 0) red[0] = r;
    }
    __syncthreads();
    float out = red[0];
    __syncthreads();
    return out;
}

__global__ __launch_bounds__(256) void ln_kernel(const float* __restrict__ x,
                                                 const float* __restrict__ b_pre) {
    __shared__ float sx[D_MODEL];
    __shared__ float red[32];
    const int row = blockIdx.x;
    const int t = threadIdx.x;
    const float* xr = x + (size_t)row * D_MODEL;

    float sum = 0.f;
    #pragma unroll
    for (int q = 0; q < 4; q++) { float f = xr[t + q * 256]; sx[t + q * 256] = f; sum += f; }
    float m = block_reduce_sum256(sum, red) * (1.0f / D_MODEL);

    float sq = 0.f;
    #pragma unroll
    for (int q = 0; q < 4; q++) { float c = sx[t + q * 256] - m; sq += c * c; }
    float sd = sqrtf(block_reduce_sum256(sq, red) * (1.0f / (D_MODEL - 1)));
    float inv = 1.0f / (sd + EPS);

    #pragma unroll
    for (int q = 0; q < 4; q++) {
        int col = t + q * 256;
        float v = (sx[col] - m) * inv - b_pre[col];
        g_xn[(size_t)row * D_MODEL + col] = v;
        sx[col] = v;
    }
    if (t == 0) { g_mu[row] = m; g_sd[row] = sd; g_ln[row] = 0; }   // zero list count
    __syncthreads();

    if (t < 128) {
        const int c = t >> 3;            // k-chunk 0..15
        const int eg = t & 7;            // 16B group within 128B row
        const int k = t * 8;
        __half2 h[4];
        #pragma unroll
        for (int j = 0; j < 4; j++)
            h[j] = __floats2half2_rn(sx[k + 2*j], sx[k + 2*j + 1]);
        const int blk = row >> 7, r = row & 127;
        char* tile = (char*)g_ap + ((size_t)blk * NCHUNK + c) * TILE_BYTES;
        *reinterpret_cast<uint4*>(tile + r * 128 + ((eg ^ (r & 7)) * 16)) =
            *reinterpret_cast<uint4*>(h);
    }
}

// ---------------- fused transpose + pack: w_enc -> g_bt fp32 + g_bp fp16 ------
__global__ __launch_bounds__(256) void transpose_pack_kernel(const float* __restrict__ w) {
    __shared__ float tile[32][33];
    const int n0 = blockIdx.x * 32, k0 = blockIdx.y * 32;
    const int tx = threadIdx.x, ty = threadIdx.y;
    const int t = ty * 32 + tx;
    #pragma unroll
    for (int i = 0; i < 32; i += 8)
        tile[ty + i][tx] = w[(size_t)(k0 + ty + i) * D_HID + n0 + tx];
    __syncthreads();
    #pragma unroll
    for (int i = 0; i < 32; i += 8)
        g_bt[(size_t)(n0 + ty + i) * D_MODEL + k0 + tx] = tile[tx][ty + i];
    if (t < 128) {
        const int r = t >> 2;            // local n row 0..31
        const int gq = t & 3;            // 8-k group 0..3
        const int n = n0 + r;
        const int k = k0 + gq * 8;
        __half2 h[4];
        #pragma unroll
        for (int j = 0; j < 4; j++)
            h[j] = __floats2half2_rn(tile[gq*8 + 2*j][r] * 256.0f,
                                     tile[gq*8 + 2*j + 1][r] * 256.0f);
        const int blk = n >> 7, c = k >> 6;
        const int r128 = n & 127;
        const int eg = (k & 63) >> 3;
        char* tp = (char*)g_bp + ((size_t)blk * NCHUNK + c) * TILE_BYTES;
        *reinterpret_cast<uint4*>(tp + r128 * 128 + ((eg ^ (r128 & 7)) * 16)) =
            *reinterpret_cast<uint4*>(h);
    }
}

// ---------------- pack w_dec -> fp16 (decode values only) ---------------------
__global__ __launch_bounds__(256) void wd_pack_kernel(const float* __restrict__ wd) {
    const size_t i = ((size_t)blockIdx.x * 256 + threadIdx.x) * 8;
    const float4 a = *reinterpret_cast<const float4*>(wd + i);
    const float4 b = *reinterpret_cast<const float4*>(wd + i + 4);
    __half2 h[4];
    h[0] = __floats2half2_rn(a.x, a.y);
    h[1] = __floats2half2_rn(a.z, a.w);
    h[2] = __floats2half2_rn(b.x, b.y);
    h[3] = __floats2half2_rn(b.z, b.w);
    *reinterpret_cast<uint4*>(g_wd + i) = *reinterpret_cast<uint4*>(h);
}

// ---------------- HMMA GEMM (f32 acc) + fused candidate extraction ------------
__device__ __forceinline__ void list_push(int row, int col, float f) {
    if (f >= FLOOR) {
        int pos = atomicAdd(&g_ln[row], 1);
        if (pos < LIST_CAP)
            g_list[(size_t)row * LIST_CAP + pos] =
                ((uint32_t)__half_as_ushort(__float2half_rn(f)) << 16) | (uint32_t)col;
    }
}

__global__ __launch_bounds__(256, 2) void enc_gemm_mma(const float* __restrict__ bias) {
    extern __shared__ __align__(1024) char smem[];
    const uint32_t sb = smem_u32(smem);
    __shared__ __align__(8) uint64_t mbar_store[2];
    const uint32_t mb0 = smem_u32(&mbar_store[0]);
    const uint32_t mb1 = smem_u32(&mbar_store[1]);

    const int t = threadIdx.x;
    const int wid = t >> 5, lane = t & 31;
    const int wm = wid >> 1, wn = wid & 1;      // 4x2 warps, warp tile 32x64
    const int Mblk = blockIdx.x;
    const int Nblk = blockIdx.y;
    const int bm = Mblk * TM;
    const int bn = Nblk * TN;

    if (t == 0) { MBAR_INIT(mb0, 1); MBAR_INIT(mb1, 1); }
    __syncthreads();

    float acc[2][8][4];
    #pragma unroll
    for (int i = 0; i < 2; i++)
        #pragma unroll
        for (int j = 0; j < 8; j++)
            #pragma unroll
            for (int q = 0; q < 4; q++) acc[i][j][q] = 0.f;

    const int laneA = lane & 15;
    const int hiA   = lane >> 4;
    const int rBoff = (lane & 7) + ((lane >> 4) << 3);
    const int hiB   = (lane >> 3) & 1;

    const char* Abase = (const char*)g_ap + (size_t)Mblk * NCHUNK * TILE_BYTES;
    const char* Bbase = (const char*)g_bp + (size_t)Nblk * NCHUNK * TILE_BYTES;

    if (t == 0) {
        MBAR_EXPECT(mb0, STAGE_BYTES);
        bulk_cp(sb,         Abase, TILE_BYTES, mb0);
        bulk_cp(sb + 16384, Bbase, TILE_BYTES, mb0);
    }

    for (int c = 0; c < NCHUNK; c++) {
        const int s = c & 1;
        if (c + 1 < NCHUNK && t == 0) {
            const uint32_t mbN = (s ? mb0 : mb1);
            const uint32_t stN = sb + (uint32_t)(1 - s) * STAGE_BYTES;
            MBAR_EXPECT(mbN, STAGE_BYTES);
            bulk_cp(stN,         Abase + (size_t)(c + 1) * TILE_BYTES, TILE_BYTES, mbN);
            bulk_cp(stN + 16384, Bbase + (size_t)(c + 1) * TILE_BYTES, TILE_BYTES, mbN);
        }
        MBAR_WAIT(s ? mb1 : mb0, (c >> 1) & 1);

        const uint32_t base = sb + (uint32_t)s * STAGE_BYTES;
        const uint32_t Ah = base, Bh = base + 16384;

        #pragma unroll
        for (int ks = 0; ks < 4; ks++) {
            const int c0 = ks * 2;
            uint32_t aH[2][4], bH[8][2];
            #pragma unroll
            for (int tm = 0; tm < 2; tm++) {
                int r = wm * 32 + tm * 16 + laneA;
                uint32_t off = (uint32_t)r * 128 + (uint32_t)((((c0 + hiA) ^ (r & 7))) * 16);
                LDSM4(aH[tm][0], aH[tm][1], aH[tm][2], aH[tm][3], Ah + off);
            }
            #pragma unroll
            for (int tp = 0; tp < 4; tp++) {
                int r = wn * 64 + tp * 16 + rBoff;
                uint32_t off = (uint32_t)r * 128 + (uint32_t)((((c0 + hiB) ^ (r & 7))) * 16);
                LDSM4(bH[2*tp][0], bH[2*tp][1], bH[2*tp+1][0], bH[2*tp+1][1], Bh + off);
            }
            #pragma unroll
            for (int tm = 0; tm < 2; tm++)
                #pragma unroll
                for (int tn = 0; tn < 8; tn++)
                    MMA16816(acc[tm][tn], aH[tm], bH[tn][0], bH[tn][1]);
        }
        __syncthreads();
    }

    // epilogue: unscale (B was x256), add bias, store fp16, push candidates
    const float inv256 = 1.0f / 256.0f;
    const int gid = lane >> 2, tig = lane & 3;
    #pragma unroll
    for (int tm = 0; tm < 2; tm++) {
        const int r0 = bm + wm * 32 + tm * 16 + gid;
        #pragma unroll
        for (int tn = 0; tn < 8; tn++) {
            const int col = bn + wn * 64 + tn * 8 + tig * 2;
            const float b0 = __ldg(&bias[col]);
            const float b1 = __ldg(&bias[col + 1]);
            const float f0 = acc[tm][tn][0] * inv256 + b0;
            const float f1 = acc[tm][tn][1] * inv256 + b1;
            const float f2 = acc[tm][tn][2] * inv256 + b0;
            const float f3 = acc[tm][tn][3] * inv256 + b1;
            *reinterpret_cast<__half2*>(&g_preh[(size_t)r0 * D_HID + col]) =
                __floats2half2_rn(f0, f1);
            *reinterpret_cast<__half2*>(&g_preh[(size_t)(r0 + 8) * D_HID + col]) =
                __floats2half2_rn(f2, f3);
            list_push(r0,     col,     f0);
            list_push(r0,     col + 1, f1);
            list_push(r0 + 8, col,     f2);
            list_push(r0 + 8, col + 1, f3);
        }
    }
}

// ---------------- topk: list-based histogram select (fallback: full row) ------
__device__ __forceinline__ int bin_of_half_bits(uint32_t h) {
    uint32_t k = (h & 0x8000u) ? ((~h) & 0xFFFFu) : (h | 0x8000u);
    return (int)(k >> 4);
}

__global__ __launch_bounds__(256) void topk_kernel() {
    __shared__ int hist[NBINS];            // 16 KB
    __shared__ int segs[256];
    __shared__ int warpTot[8];
    __shared__ float s_thr;
    __shared__ int s_cnt;

    const int row = blockIdx.x;
    const int t = threadIdx.x;
    const int lane = t & 31, wid = t >> 5;
    const int n_raw = g_ln[row];
    const bool listOK = (n_raw >= TOPK && n_raw <= LIST_CAP);
    const uint32_t* L = g_list + (size_t)row * LIST_CAP;

    if (t == 0) s_cnt = 0;
    #pragma unroll
    for (int i = 0; i < NBINS / 256; i++) hist[t + i * 256] = 0;
    __syncthreads();

    if (listOK) {
        for (int i = t; i < n_raw; i += 256)
            atomicAdd(&hist[(int)((L[i] | 0x80000000u) >> 20)], 1);
    } else {
        const uint4* p4 = reinterpret_cast<const uint4*>(g_preh + (size_t)row * D_HID);
        #pragma unroll
        for (int i = 0; i < D_HID / 8 / 256; i++) {
            const uint4 v = p4[t + i * 256];
            #pragma unroll
            for (int wsel = 0; wsel < 4; wsel++) {
                const uint32_t w = (&v.x)[wsel];
                atomicAdd(&hist[bin_of_half_bits(w & 0xFFFFu)], 1);
                atomicAdd(&hist[bin_of_half_bits(w >> 16)], 1);
            }
        }
    }
    __syncthreads();

    int seg = 0;
    #pragma unroll
    for (int k = 0; k < 16; k++) seg += hist[t * 16 + k];
    segs[t] = seg;
    int wsum = seg;
    #pragma unroll
    for (int o = 16; o > 0; o >>= 1) wsum += __shfl_xor_sync(0xffffffffu, wsum, o);
    if (lane == 0) warpTot[wid] = wsum;
    __syncthreads();

    if (t == 0) {
        int cum = 0, w = 7;
        for (; w > 0; w--) { if (cum + warpTot[w] >= TOPK) break; cum += warpTot[w]; }
        int s = w * 32 + 31;
        for (; s > w * 32; s--) { if (cum + segs[s] >= TOPK) break; cum += segs[s]; }
        int b = s * 16 + 15;
        for (; b > s * 16; b--) { if (cum + hist[b] >= TOPK) break; cum += hist[b]; }
        uint32_t keyLo = (uint32_t)b << 4;
        uint32_t hbits = (keyLo & 0x8000u) ? (keyLo & 0x7FFFu) : ((~keyLo) & 0xFFFFu);
        __half_raw hr; hr.x = (unsigned short)hbits;
        s_thr = __half2float(__half(hr)) - MARGIN;
    }
    __syncthreads();

    const float thr = s_thr;
    if (listOK && thr >= FLOOR + 0.002f) {
        for (int i = t; i < n_raw; i += 256) {
            const uint32_t e = L[i];
            __half_raw hr; hr.x = (unsigned short)(e >> 16);
            if (__half2float(__half(hr)) >= thr) {
                int pos = atomicAdd(&s_cnt, 1);
                if (pos < CAND_MAX) g_ci[(size_t)row * CAND_MAX + pos] = (int)(e & 0xFFFFu);
            }
        }
    } else {
        const __half* p = g_preh + (size_t)row * D_HID;
        for (int i = t; i < D_HID; i += 256) {
            if (__half2float(p[i]) >= thr) {
                int pos = atomicAdd(&s_cnt, 1);
                if (pos < CAND_MAX) g_ci[(size_t)row * CAND_MAX + pos] = i;
            }
        }
    }
    __syncthreads();
    if (t == 0) g_cn[row] = (s_cnt < CAND_MAX) ? s_cnt : CAND_MAX;
}

// ---------------- rescue: exact fp32 dots, cp.async double-buffered -----------
// Per-candidate FMA chain (k=0..1023, single fp32 accumulator) is byte-identical
// in order/rounding to the R1 baseline. Only the STAGING is pipelined.
__global__ __launch_bounds__(256, 2) void rescue_kernel(const float* __restrict__ b_enc) {
    extern __shared__ __align__(16) float dyn[];
    float* sx  = dyn;                                    // [D_MODEL]
    float* buf = dyn + D_MODEL;                          // [2][CAND_MAX][RPAD]
    float* sv  = buf + 2 * CAND_MAX * RPAD;              // [CAND_MAX]
    int*   si  = (int*)(sv + CAND_MAX);                  // [CAND_MAX]
    const uint32_t sbuf = smem_u32(buf);

    const int row = blockIdx.x;
    const int t = threadIdx.x;

    #pragma unroll
    for (int q = 0; q < 4; q++)
        sx[t + q * 256] = g_xn[(size_t)row * D_MODEL + t + q * 256];
    si[t] = (t < g_cn[row]) ? g_ci[(size_t)row * CAND_MAX + t] : 0x7FFFFFFF;
    __syncthreads();
    const int C = g_cn[row];
    const int myIdx = si[t];
    const int passes = (C + 31) >> 5;      // 32 candidates per pass (8 threads each)
    const int cpc = t >> 3;                // candidate lane within pass
    const int q16 = t & 7;                 // 16B quarter within 128B segment

    // stage a 32-float k-segment of every candidate row into buffer s
    auto stage = [&](int tileIdx, int s) {
        const int k0 = tileIdx * RTILE;
        for (int pass = 0; pass < passes; pass++) {
            const int c = pass * 32 + cpc;
            if (c < C)
                cp16(sbuf + (uint32_t)((s * CAND_MAX + c) * RPAD + q16 * 4) * 4,
                     g_bt + (size_t)si[c] * D_MODEL + k0 + q16 * 4);
        }
    };

    // prologue: tile 0 -> buffer 0
    stage(0, 0);
    CP_COMMIT();

    float acc = 0.f;
    for (int c = 0; c < NRTILE; c++) {
        const int s = c & 1;
        if (c + 1 < NRTILE) {
            stage(c + 1, 1 - s);
            CP_COMMIT();
            CP_WAIT(1);                    // tile c complete (tile c+1 in flight)
        } else {
            CP_WAIT(0);
        }
        __syncthreads();
        if (t < C) {
            const float* wrow = buf + (s * CAND_MAX + t) * RPAD;
            const int k0 = c * RTILE;
            #pragma unroll
            for (int kk = 0; kk < RTILE; kk++)
                acc = fmaf(sx[k0 + kk], wrow[kk], acc);   // strict sequential chain
        }
        __syncthreads();                   // compute done before buffer s is re-staged
    }

    if (t < C) {
        sv[t] = acc + __ldg(&b_enc[myIdx]);
    } else {
        sv[t] = -__int_as_float(0x7F800000);   // -inf
    }
    __syncthreads();

    // bitonic sort 256: val desc, idx asc (jax tie order)
    #pragma unroll 1
    for (int k = 2; k <= CAND_MAX; k <<= 1) {
        #pragma unroll 1
        for (int j = k >> 1; j > 0; j >>= 1) {
            const int ixj = t ^ j;
            if (ixj > t) {
                float v0 = sv[t], v1 = sv[ixj];
                int i0 = si[t], i1 = si[ixj];
                bool firstWins = (v0 > v1) || (v0 == v1 && i0 < i1);
                if (((t & k) == 0) != firstWins) {
                    sv[t] = v1; sv[ixj] = v0;
                    si[t] = i1; si[ixj] = i0;
                }
            }
            __syncthreads();
        }
    }

    if (t < TOPK) {
        g_tv[(size_t)row * TOPK + t] = fmaxf(sv[t], 0.0f);
        g_ti[(size_t)row * TOPK + t] = si[t];
    }
}

// ---------------- sparse decode (fp16 weights) + de-normalize -----------------
__global__ __launch_bounds__(256) void decode_kernel(const float* __restrict__ b_pre,
                                                     float* __restrict__ out) {
    __shared__ float sval[TOPK];
    __shared__ int   sidx[TOPK];
    const int row = blockIdx.x;
    const int t = threadIdx.x;
    if (t < TOPK) {
        sval[t] = g_tv[(size_t)row * TOPK + t];
        sidx[t] = g_ti[(size_t)row * TOPK + t];
    }
    __syncthreads();

    float2 a0 = {0.f, 0.f}, a1 = {0.f, 0.f};
    #pragma unroll 4
    for (int j = 0; j < TOPK; j++) {
        const float v = sval[j];
        const __half2* wr2 = reinterpret_cast<const __half2*>(
            g_wd + (size_t)sidx[j] * D_MODEL);
        const float2 f0 = __half22float2(__ldg(&wr2[t]));
        const float2 f1 = __half22float2(__ldg(&wr2[t + 256]));
        a0.x = fmaf(v, f0.x, a0.x); a0.y = fmaf(v, f0.y, a0.y);
        a1.x = fmaf(v, f1.x, a1.x); a1.y = fmaf(v, f1.y, a1.y);
    }
    const float m = g_mu[row], s = g_sd[row];
    float* o = out + (size_t)row * D_MODEL;
    const int c0 = 2 * t, c1 = 2 * t + 512;
    o[c0]     = (a0.x + b_pre[c0])     * s + m;
    o[c0 + 1] = (a0.y + b_pre[c0 + 1]) * s + m;
    o[c1]     = (a1.x + b_pre[c1])     * s + m;
    o[c1 + 1] = (a1.y + b_pre[c1 + 1]) * s + m;
}

// ---------------- launch ------------------------------------------------------
extern "C" void kernel_launch(void* const* d_in, const int* in_sizes, int n_in,
                              void* d_out, int out_size) {
    const float* x     = (const float*)d_in[0];
    const float* w_enc = (const float*)d_in[1];
    const float* w_dec = (const float*)d_in[2];
    const float* b_enc = (const float*)d_in[3];
    const float* b_pre = (const float*)d_in[4];
    float* out = (float*)d_out;

    // 1. LayerNorm (fp32 out + packed swizzled fp16 A tiles + list-count reset)
    ln_kernel<<<N_TOK, 256>>>(x, b_pre);

    // 2. Fused transpose + pack: w_enc -> g_bt fp32 + g_bp fp16(x256)
    dim3 tg(D_HID / 32, D_MODEL / 32);
    transpose_pack_kernel<<<tg, dim3(32, 8)>>>(w_enc);

    // 3. Pack w_dec -> fp16 (decode values only; selection path untouched)
    wd_pack_kernel<<<(int)(((size_t)D_HID * D_MODEL) / 8 / 256), 256>>>(w_dec);

    // 4. HMMA encoder GEMM (f32 acc) + fused candidate-list extraction
    cudaFuncSetAttribute(enc_gemm_mma, cudaFuncAttributeMaxDynamicSharedMemorySize, GEMM_SMEM);
    dim3 ggrid(N_TOK / TM, D_HID / TN);
    enc_gemm_mma<<<ggrid, 256, GEMM_SMEM>>>(b_enc);

    // 5. List-based histogram select (full-row fallback for safety)
    topk_kernel<<<N_TOK, 256>>>();

    // 6. Rescue: R1-identical sequential fp32 dots, cp.async double-buffered
    cudaFuncSetAttribute(rescue_kernel, cudaFuncAttributeMaxDynamicSharedMemorySize, RES_SMEM);
    rescue_kernel<<<N_TOK, 256, RES_SMEM>>>(b_enc);

    // 7. Sparse decode (fp16 weights) + un-normalize
    decode_kernel<<<N_TOK, 256>>>(b_pre, out);
}